// round 6
// baseline (speedup 1.0000x reference)
#include <cuda_runtime.h>
#include <math.h>
#include <stdint.h>

// Problem constants
#define Bp 4
#define Np 2048
#define Cp 512
#define Hp 8
#define Dp 64
#define Wp 4
#define NWp 512
#define KEEP 64

// Scratch (device globals; no allocation allowed)
__device__ float g_q[Bp*Np*Hp*Dp];       // [B,N,H,D]
__device__ float g_k[Bp*Np*Hp*Dp];
__device__ float g_v[Bp*Np*Hp*Dp];
__device__ float g_attn[Bp*Np*Hp*Dp];    // [B,N,H*D]
__device__ int   g_idx[Bp*Hp*NWp*KEEP];  // [B,H,NW,64]
__device__ float g_Wperm[Cp*3*Hp*Dp];    // Wqkv columns permuted to (s,h,d) order
__device__ float g_bperm[3*Hp*Dp];

// ---------------------------------------------------------------------------
// tf32 helpers
// ---------------------------------------------------------------------------
__device__ __forceinline__ float to_tf32(float x) {
    unsigned u;
    asm("cvt.rna.tf32.f32 %0, %1;" : "=r"(u) : "f"(x));
    return __uint_as_float(u);
}

__device__ __forceinline__ void mma_tf32(float4& d,
    unsigned a0, unsigned a1, unsigned a2, unsigned a3,
    unsigned b0, unsigned b1)
{
    asm volatile(
        "mma.sync.aligned.m16n8k8.row.col.f32.tf32.tf32.f32 "
        "{%0,%1,%2,%3}, {%4,%5,%6,%7}, {%8,%9}, {%0,%1,%2,%3};\n"
        : "+f"(d.x), "+f"(d.y), "+f"(d.z), "+f"(d.w)
        : "r"(a0), "r"(a1), "r"(a2), "r"(a3), "r"(b0), "r"(b1));
}

// ---------------------------------------------------------------------------
// Weight/bias column permutation: u = s*512 + h*64 + d  <-  c = hd*3 + s
// ---------------------------------------------------------------------------
__global__ __launch_bounds__(256) void permW_kernel(
    const float* __restrict__ Wqkv, const float* __restrict__ bqkv)
{
    int idx = blockIdx.x*256 + threadIdx.x;      // 0 .. 512*1536-1
    int u = idx % 1536;
    int k = idx / 1536;
    int s = u >> 9, hd = u & 511;
    g_Wperm[idx] = Wqkv[(size_t)k*1536 + hd*3 + s];
    if (idx < 1536) g_bperm[idx] = bqkv[(idx & 511)*3 + (idx >> 9)];
}

// ---------------------------------------------------------------------------
// tf32 tensor-core GEMM, double-buffered (one sync per k-tile).
// ---------------------------------------------------------------------------
#define AS_STRIDE 36
#define BS_STRIDE 132
#define AS_STAGE (128*AS_STRIDE)
#define BS_STAGE (32*BS_STRIDE)
#define GEMM_SMEM ((2*AS_STAGE + 2*BS_STAGE)*4)  // 70656 bytes

template<int EPI>
__global__ __launch_bounds__(256, 2) void gemm_tf32_kernel(
    const float* __restrict__ Ain,
    const float* __restrict__ BwIn,
    const float* __restrict__ biasIn,
    float* __restrict__ Cout,
    int Nn)
{
    extern __shared__ float smem[];
    float* AsB = smem;
    float* BsB = smem + 2*AS_STAGE;

    const int Kk = 512;
    const float* A    = (EPI == 0) ? Ain : (const float*)g_attn;
    const float* Bw   = (EPI == 0) ? (const float*)g_Wperm : BwIn;
    const float* bias = (EPI == 0) ? (const float*)g_bperm : biasIn;

    int tid = threadIdx.x;
    int bx = blockIdx.x, by = blockIdx.y;
    int warp = tid >> 5, lane = tid & 31;
    int wm = warp & 1, wn = warp >> 1;
    int gid = lane >> 2, tig = lane & 3;

    float4 acc[4][4];
    #pragma unroll
    for (int i = 0; i < 4; i++)
        #pragma unroll
        for (int j = 0; j < 4; j++) acc[i][j] = make_float4(0.f,0.f,0.f,0.f);

    float4 ra[4], rb[4];

    #pragma unroll
    for (int i = 0; i < 4; i++) {
        int f = tid + i*256;
        ra[i] = *(const float4*)(A + (size_t)(by*128 + (f>>3))*Kk + (f&7)*4);
        rb[i] = *(const float4*)(Bw + (size_t)(f>>5)*Nn + bx*128 + (f&31)*4);
    }
    #pragma unroll
    for (int i = 0; i < 4; i++) {
        int f = tid + i*256;
        float4 a = ra[i], b = rb[i];
        a.x = to_tf32(a.x); a.y = to_tf32(a.y); a.z = to_tf32(a.z); a.w = to_tf32(a.w);
        b.x = to_tf32(b.x); b.y = to_tf32(b.y); b.z = to_tf32(b.z); b.w = to_tf32(b.w);
        *(float4*)&AsB[(f>>3)*AS_STRIDE + (f&7)*4]  = a;
        *(float4*)&BsB[(f>>5)*BS_STRIDE + (f&31)*4] = b;
    }
    __syncthreads();

    for (int kt = 0; kt < 16; kt++) {
        int cur = kt & 1;
        const float* Asc = AsB + cur*AS_STAGE;
        const float* Bsc = BsB + cur*BS_STAGE;

        if (kt < 15) {
            int k0n = (kt+1)*32;
            #pragma unroll
            for (int i = 0; i < 4; i++) {
                int f = tid + i*256;
                ra[i] = *(const float4*)(A + (size_t)(by*128 + (f>>3))*Kk + k0n + (f&7)*4);
                rb[i] = *(const float4*)(Bw + (size_t)(k0n + (f>>5))*Nn + bx*128 + (f&31)*4);
            }
        }

        #pragma unroll
        for (int ks = 0; ks < 4; ks++) {
            int k0 = ks*8;
            unsigned af[4][4], bf[4][2];
            #pragma unroll
            for (int i = 0; i < 4; i++) {
                int r = wm*64 + i*16 + gid;
                af[i][0] = __float_as_uint(Asc[ r    *AS_STRIDE + k0 + tig]);
                af[i][1] = __float_as_uint(Asc[(r+8)*AS_STRIDE + k0 + tig]);
                af[i][2] = __float_as_uint(Asc[ r    *AS_STRIDE + k0 + tig + 4]);
                af[i][3] = __float_as_uint(Asc[(r+8)*AS_STRIDE + k0 + tig + 4]);
            }
            #pragma unroll
            for (int j = 0; j < 4; j++) {
                int c = wn*32 + j*8 + gid;
                bf[j][0] = __float_as_uint(Bsc[(k0 + tig    )*BS_STRIDE + c]);
                bf[j][1] = __float_as_uint(Bsc[(k0 + tig + 4)*BS_STRIDE + c]);
            }
            #pragma unroll
            for (int i = 0; i < 4; i++)
                #pragma unroll
                for (int j = 0; j < 4; j++)
                    mma_tf32(acc[i][j], af[i][0], af[i][1], af[i][2], af[i][3],
                             bf[j][0], bf[j][1]);
        }

        if (kt < 15) {
            float* Asn = AsB + (cur^1)*AS_STAGE;
            float* Bsn = BsB + (cur^1)*BS_STAGE;
            #pragma unroll
            for (int i = 0; i < 4; i++) {
                int f = tid + i*256;
                float4 a = ra[i], b = rb[i];
                a.x = to_tf32(a.x); a.y = to_tf32(a.y); a.z = to_tf32(a.z); a.w = to_tf32(a.w);
                b.x = to_tf32(b.x); b.y = to_tf32(b.y); b.z = to_tf32(b.z); b.w = to_tf32(b.w);
                *(float4*)&Asn[(f>>3)*AS_STRIDE + (f&7)*4]  = a;
                *(float4*)&Bsn[(f>>5)*BS_STRIDE + (f&31)*4] = b;
            }
        }
        __syncthreads();
    }

    float* dst;
    int colBase, rowStride;
    if (EPI == 0) {
        int s = bx >> 2;
        dst = (s == 0) ? g_q : (s == 1) ? g_k : g_v;
        colBase = (bx & 3)*128;
        rowStride = 512;
    } else {
        dst = Cout;
        colBase = bx*128;
        rowStride = Nn;
    }
    #pragma unroll
    for (int i = 0; i < 4; i++) {
        int m0 = by*128 + wm*64 + i*16 + gid;
        #pragma unroll
        for (int j = 0; j < 4; j++) {
            int cl = wn*32 + j*8 + tig*2;
            float bz0 = bias[bx*128 + cl];
            float bz1 = bias[bx*128 + cl + 1];
            float4 d = acc[i][j];
            float2 o0 = make_float2(d.x + bz0, d.y + bz1);
            float2 o1 = make_float2(d.z + bz0, d.w + bz1);
            *(float2*)(dst + (size_t)m0*rowStride + colBase + cl)     = o0;
            *(float2*)(dst + (size_t)(m0+8)*rowStride + colBase + cl) = o1;
        }
    }
}

// ---------------------------------------------------------------------------
// Block-wide inclusive scan (256 threads) via warp shuffles.
// ---------------------------------------------------------------------------
__device__ __forceinline__ unsigned blockScanIncl(unsigned v, unsigned* warpSums, int t)
{
    int lane = t & 31, wid = t >> 5;
    #pragma unroll
    for (int off = 1; off < 32; off <<= 1) {
        unsigned n = __shfl_up_sync(0xffffffffu, v, off);
        if (lane >= off) v += n;
    }
    if (lane == 31) warpSums[wid] = v;
    __syncthreads();
    if (wid == 0) {
        unsigned s = (lane < 8) ? warpSums[lane] : 0u;
        #pragma unroll
        for (int off = 1; off < 8; off <<= 1) {
            unsigned n = __shfl_up_sync(0xffffffffu, s, off);
            if (lane >= off) s += n;
        }
        if (lane < 8) warpSums[lane] = s;
    }
    __syncthreads();
    if (wid > 0) v += warpSums[wid - 1];
    return v;
}

template<int NB>
__device__ __forceinline__ void findThresholdBin(
    const unsigned* hist, unsigned r, unsigned* warpSums, unsigned* sOut, int t)
{
    const int PER = NB / 256;
    unsigned loc[PER];
    unsigned s = 0;
    #pragma unroll
    for (int i = 0; i < PER; i++) { loc[i] = hist[t*PER + i]; s += loc[i]; }
    unsigned incl = blockScanIncl(s, warpSums, t);
    unsigned excl = incl - s;
    if (excl < r && r <= incl) {
        unsigned cum = excl;
        #pragma unroll
        for (int i = 0; i < PER; i++) {
            if (cum + loc[i] >= r) { sOut[0] = t*PER + i; sOut[1] = cum; break; }
            cum += loc[i];
        }
    }
    __syncthreads();
}

// ---------------------------------------------------------------------------
// Selection: hierarchical radix-select (11/11/10 bits), stable sorted emit.
// ---------------------------------------------------------------------------
__global__ __launch_bounds__(256) void select_kernel(
    const float* __restrict__ pareto,        // [B,H,NW,N]
    const unsigned char* __restrict__ mask)  // [B,N] bool
{
    __shared__ unsigned hist[2048];
    __shared__ unsigned cand[2048];
    __shared__ unsigned warpSums[8];
    __shared__ unsigned sOut[2];
    __shared__ unsigned sCnt;

    int p = blockIdx.x;
    int nw = p & (NWp-1);
    int b  = p / (Hp*NWp);
    int t  = threadIdx.x;

    const float* prow = pareto + (size_t)p * Np;
    const unsigned char* mrow = mask + (size_t)b * Np;

    unsigned key[8];
    #pragma unroll
    for (int v = 0; v < 2; v++) {
        int j0 = t*8 + v*4;
        float4 nz = *(const float4*)(prow + j0);
        float noise[4] = {nz.x, nz.y, nz.z, nz.w};
        #pragma unroll
        for (int i = 0; i < 4; i++) {
            int j = j0 + i;
            int cj = j >> 2;
            float gridv = fabsf((float)(nw - cj));
            float val = gridv - noise[i];
            if (mrow[j]) val = 3.402823466e38f;
            unsigned ub = __float_as_uint(val);
            ub ^= (ub & 0x80000000u) ? 0xFFFFFFFFu : 0x80000000u;
            key[v*4 + i] = ub;
        }
    }

    #pragma unroll
    for (int i = 0; i < 8; i++) hist[t*8 + i] = 0;
    __syncthreads();
    #pragma unroll
    for (int i = 0; i < 8; i++)
        atomicAdd(&hist[key[i] >> 21], 1u);
    __syncthreads();

    unsigned r = 64;
    findThresholdBin<2048>(hist, r, warpSums, sOut, t);
    unsigned bin1 = sOut[0];
    r -= sOut[1];
    unsigned prefix = bin1 << 21;
    __syncthreads();

    if (t == 0) sCnt = 0;
    __syncthreads();
    #pragma unroll
    for (int i = 0; i < 8; i++)
        if ((key[i] >> 21) == bin1)
            cand[atomicAdd(&sCnt, 1u)] = key[i];
    __syncthreads();
    unsigned E = sCnt;

    {
        #pragma unroll
        for (int i = 0; i < 8; i++) hist[t*8 + i] = 0;
        unsigned kk[8]; int n = 0;
        for (unsigned j = t; j < E; j += 256) kk[n++] = cand[j];
        __syncthreads();
        for (int i = 0; i < n; i++)
            atomicAdd(&hist[(kk[i] >> 10) & 0x7FFu], 1u);
        __syncthreads();
        findThresholdBin<2048>(hist, r, warpSums, sOut, t);
        unsigned bin2 = sOut[0];
        r -= sOut[1];
        prefix |= bin2 << 10;
        __syncthreads();
        if (t == 0) sCnt = 0;
        __syncthreads();
        for (int i = 0; i < n; i++)
            if (((kk[i] >> 10) & 0x7FFu) == bin2)
                cand[atomicAdd(&sCnt, 1u)] = kk[i];
        __syncthreads();
        E = sCnt;
    }

    {
        #pragma unroll
        for (int i = 0; i < 4; i++) hist[t*4 + i] = 0;
        unsigned kk[8]; int n = 0;
        for (unsigned j = t; j < E; j += 256) kk[n++] = cand[j];
        __syncthreads();
        for (int i = 0; i < n; i++)
            atomicAdd(&hist[kk[i] & 0x3FFu], 1u);
        __syncthreads();
        findThresholdBin<1024>(hist, r, warpSums, sOut, t);
        unsigned bin3 = sOut[0];
        r -= sOut[1];
        prefix |= bin3;
        __syncthreads();
    }

    unsigned T = prefix;
    unsigned rr = r;

    unsigned lessC = 0, eqC = 0;
    #pragma unroll
    for (int i = 0; i < 8; i++) {
        lessC += (key[i] < T);
        eqC   += (key[i] == T);
    }
    unsigned packed = lessC | (eqC << 16);
    unsigned incl = blockScanIncl(packed, warpSums, t);
    unsigned lb = (incl & 0xFFFFu) - lessC;
    unsigned eb = (incl >> 16)     - eqC;

    int* oidx = g_idx + (size_t)p * KEEP;
    #pragma unroll
    for (int i = 0; i < 8; i++) {
        int j = t*8 + i;
        unsigned k = key[i];
        if (k < T) {
            oidx[lb + min(eb, rr)] = j;
            lb++;
        } else if (k == T) {
            if (eb < rr) oidx[lb + eb] = j;
            eb++;
        }
    }
}

// ---------------------------------------------------------------------------
// Attention: one block per (b,h,nw); 256 threads. q/k/v in [B,N,H,D].
// Dots thread map (w = t&3, z = t>>2): k-row reads are quad-broadcast and
// phase-distinct across the 8 rows per warp -> conflict-free LDS.
// ---------------------------------------------------------------------------
#define PADR 68
__global__ __launch_bounds__(256) void attn_kernel(
    const float* __restrict__ pos_bias,      // [H,N,N]
    const unsigned char* __restrict__ mask)  // [B,N]
{
    __shared__ int   sidx[KEEP];
    __shared__ float ks[KEEP][PADR];
    __shared__ float vs[KEEP][PADR];
    __shared__ float qs[Wp][PADR];
    __shared__ float sd[Wp][PADR];
    __shared__ float partial[4][Wp][Dp];

    int p  = blockIdx.x;
    int nw = p & (NWp-1);
    int bh = p >> 9;
    int h  = bh & (Hp-1);
    int b  = bh >> 3;
    int t  = threadIdx.x;

    if (t < KEEP) sidx[t] = g_idx[(size_t)p * KEEP + t];
    {
        int w = t >> 6, d = t & 63;
        qs[w][d] = g_q[((size_t)(b*Np + nw*Wp + w)*Hp + h)*Dp + d];
    }
    __syncthreads();

    // Gather K/V: 4 threads per key row (16 floats each)
    {
        int z = t >> 2, quar = t & 3;
        int row = sidx[z];
        const float* kp = g_k + ((size_t)(b*Np + row)*Hp + h)*Dp + quar*16;
        const float* vp = g_v + ((size_t)(b*Np + row)*Hp + h)*Dp + quar*16;
        #pragma unroll
        for (int i = 0; i < 4; i++) {
            int c = quar*16 + i*4;
            *(float4*)&ks[z][c] = *(const float4*)(kp + i*4);
            *(float4*)&vs[z][c] = *(const float4*)(vp + i*4);
        }
    }
    __syncthreads();

    // Dots + pos_bias + masking: thread (w = t&3, z = t>>2).
    const float scale = 0.125f;
    {
        int w = t & 3, z = t >> 2;
        int key = sidx[z];
        float pb = __ldg(pos_bias + ((size_t)h*Np + nw*Wp + w)*Np + key);
        bool qm = mask[(size_t)b*Np + nw*Wp + w] != 0;
        bool km = mask[(size_t)b*Np + key] != 0;
        float acc = 0.f;
        #pragma unroll
        for (int i = 0; i < 16; i++) {
            float4 qv = *(const float4*)&qs[w][i*4];
            float4 kv = *(const float4*)&ks[z][i*4];
            acc += qv.x*kv.x + qv.y*kv.y + qv.z*kv.z + qv.w*kv.w;
        }
        float val = acc*scale + pb;
        if (qm && km) val = -3.402823466e38f;
        sd[w][z] = val;
    }
    __syncthreads();

    // Softmax: warp w (w<4) owns row w
    if (t < 128) {
        int w = t >> 5, lane = t & 31;
        float v0 = sd[w][lane], v1 = sd[w][lane+32];
        float m = fmaxf(v0, v1);
        #pragma unroll
        for (int off = 16; off > 0; off >>= 1)
            m = fmaxf(m, __shfl_xor_sync(0xffffffffu, m, off));
        float e0 = __expf(v0 - m), e1 = __expf(v1 - m);
        float s = e0 + e1;
        #pragma unroll
        for (int off = 16; off > 0; off >>= 1)
            s += __shfl_xor_sync(0xffffffffu, s, off);
        float inv = 1.f / s;
        sd[w][lane]    = e0*inv;
        sd[w][lane+32] = e1*inv;
    }
    __syncthreads();

    // AV phase 1: thread (g,d); each vs element read once
    {
        int g = t >> 6, d = t & 63;
        float a0 = 0.f, a1 = 0.f, a2 = 0.f, a3 = 0.f;
        #pragma unroll
        for (int zi = 0; zi < 16; zi++) {
            int z = g*16 + zi;
            float vv = vs[z][d];
            a0 += sd[0][z] * vv;
            a1 += sd[1][z] * vv;
            a2 += sd[2][z] * vv;
            a3 += sd[3][z] * vv;
        }
        partial[g][0][d] = a0;
        partial[g][1][d] = a1;
        partial[g][2][d] = a2;
        partial[g][3][d] = a3;
    }
    __syncthreads();

    // AV phase 2: reduce 4 partials, write out
    {
        int w = t >> 6, d = t & 63;
        float acc = partial[0][w][d] + partial[1][w][d]
                  + partial[2][w][d] + partial[3][w][d];
        g_attn[((size_t)b*Np + nw*Wp + w)*(Hp*Dp) + h*Dp + d] = acc;
    }
}

// ---------------------------------------------------------------------------
extern "C" void kernel_launch(void* const* d_in, const int* in_sizes, int n_in,
                              void* d_out, int out_size)
{
    const float* x            = (const float*)d_in[0];
    const unsigned char* mask = (const unsigned char*)d_in[1];
    const float* pos_bias     = (const float*)d_in[2];
    const float* pareto       = (const float*)d_in[3];
    const float* Wqkv         = (const float*)d_in[4];
    const float* bqkv         = (const float*)d_in[5];
    const float* Wo           = (const float*)d_in[6];
    const float* bo           = (const float*)d_in[7];
    float* out                = (float*)d_out;

    (void)in_sizes; (void)n_in; (void)out_size;

    static cudaStream_t s2 = nullptr;
    static cudaEvent_t evFork = nullptr, evPerm = nullptr, evJoin = nullptr;
    if (s2 == nullptr) {
        cudaStreamCreateWithFlags(&s2, cudaStreamNonBlocking);
        cudaEventCreateWithFlags(&evFork, cudaEventDisableTiming);
        cudaEventCreateWithFlags(&evPerm, cudaEventDisableTiming);
        cudaEventCreateWithFlags(&evJoin, cudaEventDisableTiming);
        cudaFuncSetAttribute(gemm_tf32_kernel<0>,
            cudaFuncAttributeMaxDynamicSharedMemorySize, GEMM_SMEM);
        cudaFuncSetAttribute(gemm_tf32_kernel<1>,
            cudaFuncAttributeMaxDynamicSharedMemorySize, GEMM_SMEM);
    }

    // Fork side stream: weight permute, then selection.
    cudaEventRecord(evFork, 0);
    cudaStreamWaitEvent(s2, evFork, 0);
    permW_kernel<<<(Cp*3*Hp*Dp)/256, 256, 0, s2>>>(Wqkv, bqkv);
    cudaEventRecord(evPerm, s2);
    select_kernel<<<Bp*Hp*NWp, 256, 0, s2>>>(pareto, mask);
    cudaEventRecord(evJoin, s2);

    // QKV GEMM (needs permuted weights).
    cudaStreamWaitEvent(0, evPerm, 0);
    {
        dim3 grid(3*Hp*Dp/128, Bp*Np/128);   // 12 x 64
        gemm_tf32_kernel<0><<<grid, 256, GEMM_SMEM>>>(x, nullptr, nullptr, nullptr, 3*Hp*Dp);
    }

    // Attention (needs q/k/v and g_idx).
    cudaStreamWaitEvent(0, evJoin, 0);
    attn_kernel<<<Bp*Hp*NWp, 256>>>(pos_bias, mask);

    // Output projection.
    {
        dim3 grid(Cp/128, Bp*Np/128);        // 4 x 64
        gemm_tf32_kernel<1><<<grid, 256, GEMM_SMEM>>>(nullptr, Wo, bo, out, Cp);
    }
}

// round 7
// speedup vs baseline: 1.0924x; 1.0924x over previous
#include <cuda_runtime.h>
#include <math.h>
#include <stdint.h>

// Problem constants
#define Bp 4
#define Np 2048
#define Cp 512
#define Hp 8
#define Dp 64
#define Wp 4
#define NWp 512
#define KEEP 64

// Scratch (device globals; no allocation allowed)
__device__ float g_q[Bp*Np*Hp*Dp];       // [B,N,H,D]
__device__ float g_k[Bp*Np*Hp*Dp];
__device__ float g_v[Bp*Np*Hp*Dp];
__device__ float g_attn[Bp*Np*Hp*Dp];    // [B,N,H*D]
__device__ int   g_idx[Bp*Hp*NWp*KEEP];  // [B,H,NW,64]
__device__ float g_Wperm[Cp*3*Hp*Dp];    // Wqkv columns permuted to (s,h,d) order
__device__ float g_bperm[3*Hp*Dp];

// ---------------------------------------------------------------------------
// tf32 helpers
// ---------------------------------------------------------------------------
__device__ __forceinline__ float to_tf32(float x) {
    unsigned u;
    asm("cvt.rna.tf32.f32 %0, %1;" : "=r"(u) : "f"(x));
    return __uint_as_float(u);
}

__device__ __forceinline__ void mma_tf32(float4& d,
    unsigned a0, unsigned a1, unsigned a2, unsigned a3,
    unsigned b0, unsigned b1)
{
    asm volatile(
        "mma.sync.aligned.m16n8k8.row.col.f32.tf32.tf32.f32 "
        "{%0,%1,%2,%3}, {%4,%5,%6,%7}, {%8,%9}, {%0,%1,%2,%3};\n"
        : "+f"(d.x), "+f"(d.y), "+f"(d.z), "+f"(d.w)
        : "r"(a0), "r"(a1), "r"(a2), "r"(a3), "r"(b0), "r"(b1));
}

// ---------------------------------------------------------------------------
// Weight/bias column permutation: u = s*512 + h*64 + d  <-  c = hd*3 + s
// ---------------------------------------------------------------------------
__global__ __launch_bounds__(256) void permW_kernel(
    const float* __restrict__ Wqkv, const float* __restrict__ bqkv)
{
    int idx = blockIdx.x*256 + threadIdx.x;      // 0 .. 512*1536-1
    int u = idx % 1536;
    int k = idx / 1536;
    int s = u >> 9, hd = u & 511;
    g_Wperm[idx] = Wqkv[(size_t)k*1536 + hd*3 + s];
    if (idx < 1536) g_bperm[idx] = bqkv[(idx & 511)*3 + (idx >> 9)];
}

// ---------------------------------------------------------------------------
// tf32 tensor-core GEMM, double-buffered (one sync per k-tile).
// ---------------------------------------------------------------------------
#define AS_STRIDE 36
#define BS_STRIDE 132
#define AS_STAGE (128*AS_STRIDE)
#define BS_STAGE (32*BS_STRIDE)
#define GEMM_SMEM ((2*AS_STAGE + 2*BS_STAGE)*4)  // 70656 bytes

template<int EPI>
__global__ __launch_bounds__(256, 2) void gemm_tf32_kernel(
    const float* __restrict__ Ain,
    const float* __restrict__ BwIn,
    const float* __restrict__ biasIn,
    float* __restrict__ Cout,
    int Nn)
{
    extern __shared__ float smem[];
    float* AsB = smem;
    float* BsB = smem + 2*AS_STAGE;

    const int Kk = 512;
    const float* A    = (EPI == 0) ? Ain : (const float*)g_attn;
    const float* Bw   = (EPI == 0) ? (const float*)g_Wperm : BwIn;
    const float* bias = (EPI == 0) ? (const float*)g_bperm : biasIn;

    int tid = threadIdx.x;
    int bx = blockIdx.x, by = blockIdx.y;
    int warp = tid >> 5, lane = tid & 31;
    int wm = warp & 1, wn = warp >> 1;
    int gid = lane >> 2, tig = lane & 3;

    float4 acc[4][4];
    #pragma unroll
    for (int i = 0; i < 4; i++)
        #pragma unroll
        for (int j = 0; j < 4; j++) acc[i][j] = make_float4(0.f,0.f,0.f,0.f);

    float4 ra[4], rb[4];

    #pragma unroll
    for (int i = 0; i < 4; i++) {
        int f = tid + i*256;
        ra[i] = *(const float4*)(A + (size_t)(by*128 + (f>>3))*Kk + (f&7)*4);
        rb[i] = *(const float4*)(Bw + (size_t)(f>>5)*Nn + bx*128 + (f&31)*4);
    }
    #pragma unroll
    for (int i = 0; i < 4; i++) {
        int f = tid + i*256;
        float4 a = ra[i], b = rb[i];
        a.x = to_tf32(a.x); a.y = to_tf32(a.y); a.z = to_tf32(a.z); a.w = to_tf32(a.w);
        b.x = to_tf32(b.x); b.y = to_tf32(b.y); b.z = to_tf32(b.z); b.w = to_tf32(b.w);
        *(float4*)&AsB[(f>>3)*AS_STRIDE + (f&7)*4]  = a;
        *(float4*)&BsB[(f>>5)*BS_STRIDE + (f&31)*4] = b;
    }
    __syncthreads();

    for (int kt = 0; kt < 16; kt++) {
        int cur = kt & 1;
        const float* Asc = AsB + cur*AS_STAGE;
        const float* Bsc = BsB + cur*BS_STAGE;

        if (kt < 15) {
            int k0n = (kt+1)*32;
            #pragma unroll
            for (int i = 0; i < 4; i++) {
                int f = tid + i*256;
                ra[i] = *(const float4*)(A + (size_t)(by*128 + (f>>3))*Kk + k0n + (f&7)*4);
                rb[i] = *(const float4*)(Bw + (size_t)(k0n + (f>>5))*Nn + bx*128 + (f&31)*4);
            }
        }

        #pragma unroll
        for (int ks = 0; ks < 4; ks++) {
            int k0 = ks*8;
            unsigned af[4][4], bf[4][2];
            #pragma unroll
            for (int i = 0; i < 4; i++) {
                int r = wm*64 + i*16 + gid;
                af[i][0] = __float_as_uint(Asc[ r    *AS_STRIDE + k0 + tig]);
                af[i][1] = __float_as_uint(Asc[(r+8)*AS_STRIDE + k0 + tig]);
                af[i][2] = __float_as_uint(Asc[ r    *AS_STRIDE + k0 + tig + 4]);
                af[i][3] = __float_as_uint(Asc[(r+8)*AS_STRIDE + k0 + tig + 4]);
            }
            #pragma unroll
            for (int j = 0; j < 4; j++) {
                int c = wn*32 + j*8 + gid;
                bf[j][0] = __float_as_uint(Bsc[(k0 + tig    )*BS_STRIDE + c]);
                bf[j][1] = __float_as_uint(Bsc[(k0 + tig + 4)*BS_STRIDE + c]);
            }
            #pragma unroll
            for (int i = 0; i < 4; i++)
                #pragma unroll
                for (int j = 0; j < 4; j++)
                    mma_tf32(acc[i][j], af[i][0], af[i][1], af[i][2], af[i][3],
                             bf[j][0], bf[j][1]);
        }

        if (kt < 15) {
            float* Asn = AsB + (cur^1)*AS_STAGE;
            float* Bsn = BsB + (cur^1)*BS_STAGE;
            #pragma unroll
            for (int i = 0; i < 4; i++) {
                int f = tid + i*256;
                float4 a = ra[i], b = rb[i];
                a.x = to_tf32(a.x); a.y = to_tf32(a.y); a.z = to_tf32(a.z); a.w = to_tf32(a.w);
                b.x = to_tf32(b.x); b.y = to_tf32(b.y); b.z = to_tf32(b.z); b.w = to_tf32(b.w);
                *(float4*)&Asn[(f>>3)*AS_STRIDE + (f&7)*4]  = a;
                *(float4*)&Bsn[(f>>5)*BS_STRIDE + (f&31)*4] = b;
            }
        }
        __syncthreads();
    }

    float* dst;
    int colBase, rowStride;
    if (EPI == 0) {
        int s = bx >> 2;
        dst = (s == 0) ? g_q : (s == 1) ? g_k : g_v;
        colBase = (bx & 3)*128;
        rowStride = 512;
    } else {
        dst = Cout;
        colBase = bx*128;
        rowStride = Nn;
    }
    #pragma unroll
    for (int i = 0; i < 4; i++) {
        int m0 = by*128 + wm*64 + i*16 + gid;
        #pragma unroll
        for (int j = 0; j < 4; j++) {
            int cl = wn*32 + j*8 + tig*2;
            float bz0 = bias[bx*128 + cl];
            float bz1 = bias[bx*128 + cl + 1];
            float4 d = acc[i][j];
            float2 o0 = make_float2(d.x + bz0, d.y + bz1);
            float2 o1 = make_float2(d.z + bz0, d.w + bz1);
            *(float2*)(dst + (size_t)m0*rowStride + colBase + cl)     = o0;
            *(float2*)(dst + (size_t)(m0+8)*rowStride + colBase + cl) = o1;
        }
    }
}

// ---------------------------------------------------------------------------
// Block-wide inclusive scan (256 threads) via warp shuffles.
// ---------------------------------------------------------------------------
__device__ __forceinline__ unsigned blockScanIncl(unsigned v, unsigned* warpSums, int t)
{
    int lane = t & 31, wid = t >> 5;
    #pragma unroll
    for (int off = 1; off < 32; off <<= 1) {
        unsigned n = __shfl_up_sync(0xffffffffu, v, off);
        if (lane >= off) v += n;
    }
    if (lane == 31) warpSums[wid] = v;
    __syncthreads();
    if (wid == 0) {
        unsigned s = (lane < 8) ? warpSums[lane] : 0u;
        #pragma unroll
        for (int off = 1; off < 8; off <<= 1) {
            unsigned n = __shfl_up_sync(0xffffffffu, s, off);
            if (lane >= off) s += n;
        }
        if (lane < 8) warpSums[lane] = s;
    }
    __syncthreads();
    if (wid > 0) v += warpSums[wid - 1];
    return v;
}

template<int NB>
__device__ __forceinline__ void findThresholdBin(
    const unsigned* hist, unsigned r, unsigned* warpSums, unsigned* sOut, int t)
{
    const int PER = NB / 256;
    unsigned loc[PER];
    unsigned s = 0;
    #pragma unroll
    for (int i = 0; i < PER; i++) { loc[i] = hist[t*PER + i]; s += loc[i]; }
    unsigned incl = blockScanIncl(s, warpSums, t);
    unsigned excl = incl - s;
    if (excl < r && r <= incl) {
        unsigned cum = excl;
        #pragma unroll
        for (int i = 0; i < PER; i++) {
            if (cum + loc[i] >= r) { sOut[0] = t*PER + i; sOut[1] = cum; break; }
            cum += loc[i];
        }
    }
    __syncthreads();
}

// ---------------------------------------------------------------------------
// Selection: hierarchical radix-select (11/11/10 bits), stable sorted emit.
// ---------------------------------------------------------------------------
__global__ __launch_bounds__(256) void select_kernel(
    const float* __restrict__ pareto,        // [B,H,NW,N]
    const unsigned char* __restrict__ mask)  // [B,N] bool
{
    __shared__ unsigned hist[2048];
    __shared__ unsigned cand[2048];
    __shared__ unsigned warpSums[8];
    __shared__ unsigned sOut[2];
    __shared__ unsigned sCnt;

    int p = blockIdx.x;
    int nw = p & (NWp-1);
    int b  = p / (Hp*NWp);
    int t  = threadIdx.x;

    const float* prow = pareto + (size_t)p * Np;
    const unsigned char* mrow = mask + (size_t)b * Np;

    unsigned key[8];
    #pragma unroll
    for (int v = 0; v < 2; v++) {
        int j0 = t*8 + v*4;
        float4 nz = *(const float4*)(prow + j0);
        float noise[4] = {nz.x, nz.y, nz.z, nz.w};
        #pragma unroll
        for (int i = 0; i < 4; i++) {
            int j = j0 + i;
            int cj = j >> 2;
            float gridv = fabsf((float)(nw - cj));
            float val = gridv - noise[i];
            if (mrow[j]) val = 3.402823466e38f;
            unsigned ub = __float_as_uint(val);
            ub ^= (ub & 0x80000000u) ? 0xFFFFFFFFu : 0x80000000u;
            key[v*4 + i] = ub;
        }
    }

    #pragma unroll
    for (int i = 0; i < 8; i++) hist[t*8 + i] = 0;
    __syncthreads();
    #pragma unroll
    for (int i = 0; i < 8; i++)
        atomicAdd(&hist[key[i] >> 21], 1u);
    __syncthreads();

    unsigned r = 64;
    findThresholdBin<2048>(hist, r, warpSums, sOut, t);
    unsigned bin1 = sOut[0];
    r -= sOut[1];
    unsigned prefix = bin1 << 21;
    __syncthreads();

    if (t == 0) sCnt = 0;
    __syncthreads();
    #pragma unroll
    for (int i = 0; i < 8; i++)
        if ((key[i] >> 21) == bin1)
            cand[atomicAdd(&sCnt, 1u)] = key[i];
    __syncthreads();
    unsigned E = sCnt;

    {
        #pragma unroll
        for (int i = 0; i < 8; i++) hist[t*8 + i] = 0;
        unsigned kk[8]; int n = 0;
        for (unsigned j = t; j < E; j += 256) kk[n++] = cand[j];
        __syncthreads();
        for (int i = 0; i < n; i++)
            atomicAdd(&hist[(kk[i] >> 10) & 0x7FFu], 1u);
        __syncthreads();
        findThresholdBin<2048>(hist, r, warpSums, sOut, t);
        unsigned bin2 = sOut[0];
        r -= sOut[1];
        prefix |= bin2 << 10;
        __syncthreads();
        if (t == 0) sCnt = 0;
        __syncthreads();
        for (int i = 0; i < n; i++)
            if (((kk[i] >> 10) & 0x7FFu) == bin2)
                cand[atomicAdd(&sCnt, 1u)] = kk[i];
        __syncthreads();
        E = sCnt;
    }

    {
        #pragma unroll
        for (int i = 0; i < 4; i++) hist[t*4 + i] = 0;
        unsigned kk[8]; int n = 0;
        for (unsigned j = t; j < E; j += 256) kk[n++] = cand[j];
        __syncthreads();
        for (int i = 0; i < n; i++)
            atomicAdd(&hist[kk[i] & 0x3FFu], 1u);
        __syncthreads();
        findThresholdBin<1024>(hist, r, warpSums, sOut, t);
        unsigned bin3 = sOut[0];
        r -= sOut[1];
        prefix |= bin3;
        __syncthreads();
    }

    unsigned T = prefix;
    unsigned rr = r;

    unsigned lessC = 0, eqC = 0;
    #pragma unroll
    for (int i = 0; i < 8; i++) {
        lessC += (key[i] < T);
        eqC   += (key[i] == T);
    }
    unsigned packed = lessC | (eqC << 16);
    unsigned incl = blockScanIncl(packed, warpSums, t);
    unsigned lb = (incl & 0xFFFFu) - lessC;
    unsigned eb = (incl >> 16)     - eqC;

    int* oidx = g_idx + (size_t)p * KEEP;
    #pragma unroll
    for (int i = 0; i < 8; i++) {
        int j = t*8 + i;
        unsigned k = key[i];
        if (k < T) {
            oidx[lb + min(eb, rr)] = j;
            lb++;
        } else if (k == T) {
            if (eb < rr) oidx[lb + eb] = j;
            eb++;
        }
    }
}

// ---------------------------------------------------------------------------
// Attention: one block per (b,h,nw); 256 threads. q/k/v in [B,N,H,D].
// K staged in smem; V read directly from global in AV (each element once,
// 128B-coalesced per warp). sd consumed via float4 broadcast LDS.
// ---------------------------------------------------------------------------
#define PADR 68
__global__ __launch_bounds__(256) void attn_kernel(
    const float* __restrict__ pos_bias,      // [H,N,N]
    const unsigned char* __restrict__ mask)  // [B,N]
{
    __shared__ int   sidx[KEEP];
    __shared__ float ks[KEEP][PADR];
    __shared__ float qs[Wp][PADR];
    __shared__ float sd[Wp][PADR];
    __shared__ float partial[4][Wp][Dp];

    int p  = blockIdx.x;
    int nw = p & (NWp-1);
    int bh = p >> 9;
    int h  = bh & (Hp-1);
    int b  = bh >> 3;
    int t  = threadIdx.x;

    if (t < KEEP) sidx[t] = g_idx[(size_t)p * KEEP + t];
    {
        int w = t >> 6, d = t & 63;
        qs[w][d] = g_q[((size_t)(b*Np + nw*Wp + w)*Hp + h)*Dp + d];
    }
    __syncthreads();

    // Gather K only: 4 threads per key row (16 floats each)
    {
        int z = t >> 2, quar = t & 3;
        int row = sidx[z];
        const float* kp = g_k + ((size_t)(b*Np + row)*Hp + h)*Dp + quar*16;
        #pragma unroll
        for (int i = 0; i < 4; i++)
            *(float4*)&ks[z][quar*16 + i*4] = *(const float4*)(kp + i*4);
    }
    __syncthreads();

    // Dots + pos_bias + masking: thread (w = t&3, z = t>>2)
    const float scale = 0.125f;
    {
        int w = t & 3, z = t >> 2;
        int key = sidx[z];
        float pb = __ldg(pos_bias + ((size_t)h*Np + nw*Wp + w)*Np + key);
        bool qm = mask[(size_t)b*Np + nw*Wp + w] != 0;
        bool km = mask[(size_t)b*Np + key] != 0;
        float acc = 0.f;
        #pragma unroll
        for (int i = 0; i < 16; i++) {
            float4 qv = *(const float4*)&qs[w][i*4];
            float4 kv = *(const float4*)&ks[z][i*4];
            acc += qv.x*kv.x + qv.y*kv.y + qv.z*kv.z + qv.w*kv.w;
        }
        float val = acc*scale + pb;
        if (qm && km) val = -3.402823466e38f;
        sd[w][z] = val;
    }
    __syncthreads();

    // Softmax: warp w (w<4) owns row w
    if (t < 128) {
        int w = t >> 5, lane = t & 31;
        float v0 = sd[w][lane], v1 = sd[w][lane+32];
        float m = fmaxf(v0, v1);
        #pragma unroll
        for (int off = 16; off > 0; off >>= 1)
            m = fmaxf(m, __shfl_xor_sync(0xffffffffu, m, off));
        float e0 = __expf(v0 - m), e1 = __expf(v1 - m);
        float s = e0 + e1;
        #pragma unroll
        for (int off = 16; off > 0; off >>= 1)
            s += __shfl_xor_sync(0xffffffffu, s, off);
        float inv = 1.f / s;
        sd[w][lane]    = e0*inv;
        sd[w][lane+32] = e1*inv;
    }
    __syncthreads();

    // AV phase 1: thread (g = t>>6, d = t&63).
    // sd read as float4 broadcasts; v read directly from global (coalesced:
    // per warp one row x 32 consecutive d).
    {
        int g = t >> 6, d = t & 63;
        const float* vbase = g_v + ((size_t)b*Np*Hp + h)*Dp + d;
        float a0 = 0.f, a1 = 0.f, a2 = 0.f, a3 = 0.f;
        #pragma unroll
        for (int c = 0; c < 4; c++) {
            float4 s0 = *(const float4*)&sd[0][g*16 + c*4];
            float4 s1 = *(const float4*)&sd[1][g*16 + c*4];
            float4 s2 = *(const float4*)&sd[2][g*16 + c*4];
            float4 s3 = *(const float4*)&sd[3][g*16 + c*4];
            float sv0[4] = {s0.x, s0.y, s0.z, s0.w};
            float sv1[4] = {s1.x, s1.y, s1.z, s1.w};
            float sv2[4] = {s2.x, s2.y, s2.z, s2.w};
            float sv3[4] = {s3.x, s3.y, s3.z, s3.w};
            #pragma unroll
            for (int j = 0; j < 4; j++) {
                int z = g*16 + c*4 + j;
                int row = sidx[z];
                float vv = __ldg(vbase + (size_t)row*Hp*Dp);
                a0 += sv0[j] * vv;
                a1 += sv1[j] * vv;
                a2 += sv2[j] * vv;
                a3 += sv3[j] * vv;
            }
        }
        partial[g][0][d] = a0;
        partial[g][1][d] = a1;
        partial[g][2][d] = a2;
        partial[g][3][d] = a3;
    }
    __syncthreads();

    // AV phase 2: reduce 4 partials, write out
    {
        int w = t >> 6, d = t & 63;
        float acc = partial[0][w][d] + partial[1][w][d]
                  + partial[2][w][d] + partial[3][w][d];
        g_attn[((size_t)b*Np + nw*Wp + w)*(Hp*Dp) + h*Dp + d] = acc;
    }
}

// ---------------------------------------------------------------------------
extern "C" void kernel_launch(void* const* d_in, const int* in_sizes, int n_in,
                              void* d_out, int out_size)
{
    const float* x            = (const float*)d_in[0];
    const unsigned char* mask = (const unsigned char*)d_in[1];
    const float* pos_bias     = (const float*)d_in[2];
    const float* pareto       = (const float*)d_in[3];
    const float* Wqkv         = (const float*)d_in[4];
    const float* bqkv         = (const float*)d_in[5];
    const float* Wo           = (const float*)d_in[6];
    const float* bo           = (const float*)d_in[7];
    float* out                = (float*)d_out;

    (void)in_sizes; (void)n_in; (void)out_size;

    static cudaStream_t s2 = nullptr;
    static cudaEvent_t evFork = nullptr, evPerm = nullptr, evJoin = nullptr;
    if (s2 == nullptr) {
        cudaStreamCreateWithFlags(&s2, cudaStreamNonBlocking);
        cudaEventCreateWithFlags(&evFork, cudaEventDisableTiming);
        cudaEventCreateWithFlags(&evPerm, cudaEventDisableTiming);
        cudaEventCreateWithFlags(&evJoin, cudaEventDisableTiming);
        cudaFuncSetAttribute(gemm_tf32_kernel<0>,
            cudaFuncAttributeMaxDynamicSharedMemorySize, GEMM_SMEM);
        cudaFuncSetAttribute(gemm_tf32_kernel<1>,
            cudaFuncAttributeMaxDynamicSharedMemorySize, GEMM_SMEM);
    }

    // Fork side stream: weight permute, then selection.
    cudaEventRecord(evFork, 0);
    cudaStreamWaitEvent(s2, evFork, 0);
    permW_kernel<<<(Cp*3*Hp*Dp)/256, 256, 0, s2>>>(Wqkv, bqkv);
    cudaEventRecord(evPerm, s2);
    select_kernel<<<Bp*Hp*NWp, 256, 0, s2>>>(pareto, mask);
    cudaEventRecord(evJoin, s2);

    // QKV GEMM (needs permuted weights).
    cudaStreamWaitEvent(0, evPerm, 0);
    {
        dim3 grid(3*Hp*Dp/128, Bp*Np/128);   // 12 x 64
        gemm_tf32_kernel<0><<<grid, 256, GEMM_SMEM>>>(x, nullptr, nullptr, nullptr, 3*Hp*Dp);
    }

    // Attention (needs q/k/v and g_idx).
    cudaStreamWaitEvent(0, evJoin, 0);
    attn_kernel<<<Bp*Hp*NWp, 256>>>(pos_bias, mask);

    // Output projection.
    {
        dim3 grid(Cp/128, Bp*Np/128);        // 4 x 64
        gemm_tf32_kernel<1><<<grid, 256, GEMM_SMEM>>>(nullptr, Wo, bo, out, Cp);
    }
}

// round 8
// speedup vs baseline: 1.1046x; 1.0112x over previous
#include <cuda_runtime.h>
#include <math.h>
#include <stdint.h>

// Problem constants
#define Bp 4
#define Np 2048
#define Cp 512
#define Hp 8
#define Dp 64
#define Wp 4
#define NWp 512
#define KEEP 64

// Scratch (device globals; no allocation allowed)
__device__ float g_q[Bp*Np*Hp*Dp];       // [B,N,H,D]
__device__ float g_k[Bp*Np*Hp*Dp];
__device__ float g_v[Bp*Np*Hp*Dp];
__device__ float g_attn[Bp*Np*Hp*Dp];    // [B,N,H*D]
__device__ int   g_idx[Bp*Hp*NWp*KEEP];  // [B,H,NW,64]
__device__ float g_Wperm[Cp*3*Hp*Dp];    // Wqkv columns permuted to (s,h,d) order
__device__ float g_bperm[3*Hp*Dp];

// ---------------------------------------------------------------------------
// tf32 helpers
// ---------------------------------------------------------------------------
__device__ __forceinline__ float to_tf32(float x) {
    unsigned u;
    asm("cvt.rna.tf32.f32 %0, %1;" : "=r"(u) : "f"(x));
    return __uint_as_float(u);
}

__device__ __forceinline__ void mma_tf32(float4& d,
    unsigned a0, unsigned a1, unsigned a2, unsigned a3,
    unsigned b0, unsigned b1)
{
    asm volatile(
        "mma.sync.aligned.m16n8k8.row.col.f32.tf32.tf32.f32 "
        "{%0,%1,%2,%3}, {%4,%5,%6,%7}, {%8,%9}, {%0,%1,%2,%3};\n"
        : "+f"(d.x), "+f"(d.y), "+f"(d.z), "+f"(d.w)
        : "r"(a0), "r"(a1), "r"(a2), "r"(a3), "r"(b0), "r"(b1));
}

// ---------------------------------------------------------------------------
// Weight/bias column permutation: u = s*512 + h*64 + d  <-  c = hd*3 + s
// ---------------------------------------------------------------------------
__global__ __launch_bounds__(256) void permW_kernel(
    const float* __restrict__ Wqkv, const float* __restrict__ bqkv)
{
    int idx = blockIdx.x*256 + threadIdx.x;      // 0 .. 512*1536-1
    int u = idx % 1536;
    int k = idx / 1536;
    int s = u >> 9, hd = u & 511;
    g_Wperm[idx] = Wqkv[(size_t)k*1536 + hd*3 + s];
    if (idx < 1536) g_bperm[idx] = bqkv[(idx & 511)*3 + (idx >> 9)];
}

// ---------------------------------------------------------------------------
// tf32 tensor-core GEMM, double-buffered (one sync per k-tile).
// ---------------------------------------------------------------------------
#define AS_STRIDE 36
#define BS_STRIDE 132
#define AS_STAGE (128*AS_STRIDE)
#define BS_STAGE (32*BS_STRIDE)
#define GEMM_SMEM ((2*AS_STAGE + 2*BS_STAGE)*4)  // 70656 bytes

template<int EPI>
__global__ __launch_bounds__(256, 2) void gemm_tf32_kernel(
    const float* __restrict__ Ain,
    const float* __restrict__ BwIn,
    const float* __restrict__ biasIn,
    float* __restrict__ Cout,
    int Nn)
{
    extern __shared__ float smem[];
    float* AsB = smem;
    float* BsB = smem + 2*AS_STAGE;

    const int Kk = 512;
    const float* A    = (EPI == 0) ? Ain : (const float*)g_attn;
    const float* Bw   = (EPI == 0) ? (const float*)g_Wperm : BwIn;
    const float* bias = (EPI == 0) ? (const float*)g_bperm : biasIn;

    int tid = threadIdx.x;
    int bx = blockIdx.x, by = blockIdx.y;
    int warp = tid >> 5, lane = tid & 31;
    int wm = warp & 1, wn = warp >> 1;
    int gid = lane >> 2, tig = lane & 3;

    float4 acc[4][4];
    #pragma unroll
    for (int i = 0; i < 4; i++)
        #pragma unroll
        for (int j = 0; j < 4; j++) acc[i][j] = make_float4(0.f,0.f,0.f,0.f);

    float4 ra[4], rb[4];

    #pragma unroll
    for (int i = 0; i < 4; i++) {
        int f = tid + i*256;
        ra[i] = *(const float4*)(A + (size_t)(by*128 + (f>>3))*Kk + (f&7)*4);
        rb[i] = *(const float4*)(Bw + (size_t)(f>>5)*Nn + bx*128 + (f&31)*4);
    }
    #pragma unroll
    for (int i = 0; i < 4; i++) {
        int f = tid + i*256;
        float4 a = ra[i], b = rb[i];
        a.x = to_tf32(a.x); a.y = to_tf32(a.y); a.z = to_tf32(a.z); a.w = to_tf32(a.w);
        b.x = to_tf32(b.x); b.y = to_tf32(b.y); b.z = to_tf32(b.z); b.w = to_tf32(b.w);
        *(float4*)&AsB[(f>>3)*AS_STRIDE + (f&7)*4]  = a;
        *(float4*)&BsB[(f>>5)*BS_STRIDE + (f&31)*4] = b;
    }
    __syncthreads();

    for (int kt = 0; kt < 16; kt++) {
        int cur = kt & 1;
        const float* Asc = AsB + cur*AS_STAGE;
        const float* Bsc = BsB + cur*BS_STAGE;

        if (kt < 15) {
            int k0n = (kt+1)*32;
            #pragma unroll
            for (int i = 0; i < 4; i++) {
                int f = tid + i*256;
                ra[i] = *(const float4*)(A + (size_t)(by*128 + (f>>3))*Kk + k0n + (f&7)*4);
                rb[i] = *(const float4*)(Bw + (size_t)(k0n + (f>>5))*Nn + bx*128 + (f&31)*4);
            }
        }

        #pragma unroll
        for (int ks = 0; ks < 4; ks++) {
            int k0 = ks*8;
            unsigned af[4][4], bf[4][2];
            #pragma unroll
            for (int i = 0; i < 4; i++) {
                int r = wm*64 + i*16 + gid;
                af[i][0] = __float_as_uint(Asc[ r    *AS_STRIDE + k0 + tig]);
                af[i][1] = __float_as_uint(Asc[(r+8)*AS_STRIDE + k0 + tig]);
                af[i][2] = __float_as_uint(Asc[ r    *AS_STRIDE + k0 + tig + 4]);
                af[i][3] = __float_as_uint(Asc[(r+8)*AS_STRIDE + k0 + tig + 4]);
            }
            #pragma unroll
            for (int j = 0; j < 4; j++) {
                int c = wn*32 + j*8 + gid;
                bf[j][0] = __float_as_uint(Bsc[(k0 + tig    )*BS_STRIDE + c]);
                bf[j][1] = __float_as_uint(Bsc[(k0 + tig + 4)*BS_STRIDE + c]);
            }
            #pragma unroll
            for (int i = 0; i < 4; i++)
                #pragma unroll
                for (int j = 0; j < 4; j++)
                    mma_tf32(acc[i][j], af[i][0], af[i][1], af[i][2], af[i][3],
                             bf[j][0], bf[j][1]);
        }

        if (kt < 15) {
            float* Asn = AsB + (cur^1)*AS_STAGE;
            float* Bsn = BsB + (cur^1)*BS_STAGE;
            #pragma unroll
            for (int i = 0; i < 4; i++) {
                int f = tid + i*256;
                float4 a = ra[i], b = rb[i];
                a.x = to_tf32(a.x); a.y = to_tf32(a.y); a.z = to_tf32(a.z); a.w = to_tf32(a.w);
                b.x = to_tf32(b.x); b.y = to_tf32(b.y); b.z = to_tf32(b.z); b.w = to_tf32(b.w);
                *(float4*)&Asn[(f>>3)*AS_STRIDE + (f&7)*4]  = a;
                *(float4*)&Bsn[(f>>5)*BS_STRIDE + (f&31)*4] = b;
            }
        }
        __syncthreads();
    }

    float* dst;
    int colBase, rowStride;
    if (EPI == 0) {
        int s = bx >> 2;
        dst = (s == 0) ? g_q : (s == 1) ? g_k : g_v;
        colBase = (bx & 3)*128;
        rowStride = 512;
    } else {
        dst = Cout;
        colBase = bx*128;
        rowStride = Nn;
    }
    #pragma unroll
    for (int i = 0; i < 4; i++) {
        int m0 = by*128 + wm*64 + i*16 + gid;
        #pragma unroll
        for (int j = 0; j < 4; j++) {
            int cl = wn*32 + j*8 + tig*2;
            float bz0 = bias[bx*128 + cl];
            float bz1 = bias[bx*128 + cl + 1];
            float4 d = acc[i][j];
            float2 o0 = make_float2(d.x + bz0, d.y + bz1);
            float2 o1 = make_float2(d.z + bz0, d.w + bz1);
            *(float2*)(dst + (size_t)m0*rowStride + colBase + cl)     = o0;
            *(float2*)(dst + (size_t)(m0+8)*rowStride + colBase + cl) = o1;
        }
    }
}

// ---------------------------------------------------------------------------
// Block-wide inclusive scan (256 threads) via warp shuffles.
// ---------------------------------------------------------------------------
__device__ __forceinline__ unsigned blockScanIncl(unsigned v, unsigned* warpSums, int t)
{
    int lane = t & 31, wid = t >> 5;
    #pragma unroll
    for (int off = 1; off < 32; off <<= 1) {
        unsigned n = __shfl_up_sync(0xffffffffu, v, off);
        if (lane >= off) v += n;
    }
    if (lane == 31) warpSums[wid] = v;
    __syncthreads();
    if (wid == 0) {
        unsigned s = (lane < 8) ? warpSums[lane] : 0u;
        #pragma unroll
        for (int off = 1; off < 8; off <<= 1) {
            unsigned n = __shfl_up_sync(0xffffffffu, s, off);
            if (lane >= off) s += n;
        }
        if (lane < 8) warpSums[lane] = s;
    }
    __syncthreads();
    if (wid > 0) v += warpSums[wid - 1];
    return v;
}

template<int NB>
__device__ __forceinline__ void findThresholdBin(
    const unsigned* hist, unsigned r, unsigned* warpSums, unsigned* sOut, int t)
{
    const int PER = NB / 256;
    unsigned loc[PER];
    unsigned s = 0;
    #pragma unroll
    for (int i = 0; i < PER; i++) { loc[i] = hist[t*PER + i]; s += loc[i]; }
    unsigned incl = blockScanIncl(s, warpSums, t);
    unsigned excl = incl - s;
    if (excl < r && r <= incl) {
        unsigned cum = excl;
        #pragma unroll
        for (int i = 0; i < PER; i++) {
            if (cum + loc[i] >= r) { sOut[0] = t*PER + i; sOut[1] = cum; break; }
            cum += loc[i];
        }
    }
    __syncthreads();
}

// ---------------------------------------------------------------------------
// Selection: hierarchical radix-select (11/11/10 bits), stable sorted emit.
// ---------------------------------------------------------------------------
__global__ __launch_bounds__(256) void select_kernel(
    const float* __restrict__ pareto,        // [B,H,NW,N]
    const unsigned char* __restrict__ mask)  // [B,N] bool
{
    __shared__ unsigned hist[2048];
    __shared__ unsigned cand[2048];
    __shared__ unsigned warpSums[8];
    __shared__ unsigned sOut[2];
    __shared__ unsigned sCnt;

    int p = blockIdx.x;
    int nw = p & (NWp-1);
    int b  = p / (Hp*NWp);
    int t  = threadIdx.x;

    const float* prow = pareto + (size_t)p * Np;
    const unsigned char* mrow = mask + (size_t)b * Np;

    unsigned key[8];
    #pragma unroll
    for (int v = 0; v < 2; v++) {
        int j0 = t*8 + v*4;
        float4 nz = *(const float4*)(prow + j0);
        float noise[4] = {nz.x, nz.y, nz.z, nz.w};
        #pragma unroll
        for (int i = 0; i < 4; i++) {
            int j = j0 + i;
            int cj = j >> 2;
            float gridv = fabsf((float)(nw - cj));
            float val = gridv - noise[i];
            if (mrow[j]) val = 3.402823466e38f;
            unsigned ub = __float_as_uint(val);
            ub ^= (ub & 0x80000000u) ? 0xFFFFFFFFu : 0x80000000u;
            key[v*4 + i] = ub;
        }
    }

    #pragma unroll
    for (int i = 0; i < 8; i++) hist[t*8 + i] = 0;
    __syncthreads();
    #pragma unroll
    for (int i = 0; i < 8; i++)
        atomicAdd(&hist[key[i] >> 21], 1u);
    __syncthreads();

    unsigned r = 64;
    findThresholdBin<2048>(hist, r, warpSums, sOut, t);
    unsigned bin1 = sOut[0];
    r -= sOut[1];
    unsigned prefix = bin1 << 21;
    __syncthreads();

    if (t == 0) sCnt = 0;
    __syncthreads();
    #pragma unroll
    for (int i = 0; i < 8; i++)
        if ((key[i] >> 21) == bin1)
            cand[atomicAdd(&sCnt, 1u)] = key[i];
    __syncthreads();
    unsigned E = sCnt;

    {
        #pragma unroll
        for (int i = 0; i < 8; i++) hist[t*8 + i] = 0;
        unsigned kk[8]; int n = 0;
        for (unsigned j = t; j < E; j += 256) kk[n++] = cand[j];
        __syncthreads();
        for (int i = 0; i < n; i++)
            atomicAdd(&hist[(kk[i] >> 10) & 0x7FFu], 1u);
        __syncthreads();
        findThresholdBin<2048>(hist, r, warpSums, sOut, t);
        unsigned bin2 = sOut[0];
        r -= sOut[1];
        prefix |= bin2 << 10;
        __syncthreads();
        if (t == 0) sCnt = 0;
        __syncthreads();
        for (int i = 0; i < n; i++)
            if (((kk[i] >> 10) & 0x7FFu) == bin2)
                cand[atomicAdd(&sCnt, 1u)] = kk[i];
        __syncthreads();
        E = sCnt;
    }

    {
        #pragma unroll
        for (int i = 0; i < 4; i++) hist[t*4 + i] = 0;
        unsigned kk[8]; int n = 0;
        for (unsigned j = t; j < E; j += 256) kk[n++] = cand[j];
        __syncthreads();
        for (int i = 0; i < n; i++)
            atomicAdd(&hist[kk[i] & 0x3FFu], 1u);
        __syncthreads();
        findThresholdBin<1024>(hist, r, warpSums, sOut, t);
        unsigned bin3 = sOut[0];
        r -= sOut[1];
        prefix |= bin3;
        __syncthreads();
    }

    unsigned T = prefix;
    unsigned rr = r;

    unsigned lessC = 0, eqC = 0;
    #pragma unroll
    for (int i = 0; i < 8; i++) {
        lessC += (key[i] < T);
        eqC   += (key[i] == T);
    }
    unsigned packed = lessC | (eqC << 16);
    unsigned incl = blockScanIncl(packed, warpSums, t);
    unsigned lb = (incl & 0xFFFFu) - lessC;
    unsigned eb = (incl >> 16)     - eqC;

    int* oidx = g_idx + (size_t)p * KEEP;
    #pragma unroll
    for (int i = 0; i < 8; i++) {
        int j = t*8 + i;
        unsigned k = key[i];
        if (k < T) {
            oidx[lb + min(eb, rr)] = j;
            lb++;
        } else if (k == T) {
            if (eb < rr) oidx[lb + eb] = j;
            eb++;
        }
    }
}

// ---------------------------------------------------------------------------
// Attention: one block per (b,h,nw); 256 threads. q/k/v in [B,N,H,D].
// K never staged: thread (z,quar) loads its 16 K floats to registers,
// computes quad-partial dots for all 4 windows, reduces via shfl_xor.
// V read directly from global in AV. sd via float4 broadcast LDS.
// ---------------------------------------------------------------------------
#define PADR 68
__global__ __launch_bounds__(256) void attn_kernel(
    const float* __restrict__ pos_bias,      // [H,N,N]
    const unsigned char* __restrict__ mask)  // [B,N]
{
    __shared__ int   sidx[KEEP];
    __shared__ float qs[Wp][PADR];
    __shared__ float sd[Wp][PADR];
    __shared__ float partial[4][Wp][Dp];

    int p  = blockIdx.x;
    int nw = p & (NWp-1);
    int bh = p >> 9;
    int h  = bh & (Hp-1);
    int b  = bh >> 3;
    int t  = threadIdx.x;

    if (t < KEEP) sidx[t] = g_idx[(size_t)p * KEEP + t];
    {
        int w = t >> 6, d = t & 63;
        qs[w][d] = g_q[((size_t)(b*Np + nw*Wp + w)*Hp + h)*Dp + d];
    }
    __syncthreads();

    // Fused gather+dots: thread (z = t>>2, quar = t&3).
    const float scale = 0.125f;
    {
        int z = t >> 2, quar = t & 3;
        int row = sidx[z];
        const float* kp = g_k + ((size_t)(b*Np + row)*Hp + h)*Dp + quar*16;
        float4 kv[4];
        #pragma unroll
        for (int i = 0; i < 4; i++) kv[i] = __ldg((const float4*)(kp + i*4));

        // pb for (w = quar, z); masks
        float pb = __ldg(pos_bias + ((size_t)h*Np + nw*Wp + quar)*Np + row);
        bool qm = mask[(size_t)b*Np + nw*Wp + quar] != 0;
        bool km = mask[(size_t)b*Np + row] != 0;

        float pw[4] = {0.f, 0.f, 0.f, 0.f};
        #pragma unroll
        for (int i = 0; i < 4; i++) {
            #pragma unroll
            for (int w = 0; w < 4; w++) {
                float4 qv = *(const float4*)&qs[w][quar*16 + i*4];
                pw[w] += qv.x*kv[i].x + qv.y*kv[i].y + qv.z*kv[i].z + qv.w*kv[i].w;
            }
        }
        // quad reduction: lanes {4z..4z+3} sum their quarters
        #pragma unroll
        for (int w = 0; w < 4; w++) {
            pw[w] += __shfl_xor_sync(0xffffffffu, pw[w], 1);
            pw[w] += __shfl_xor_sync(0xffffffffu, pw[w], 2);
        }
        float val = pw[quar]*scale + pb;
        if (qm && km) val = -3.402823466e38f;
        sd[quar][z] = val;
    }
    __syncthreads();

    // Softmax: warp w (w<4) owns row w
    if (t < 128) {
        int w = t >> 5, lane = t & 31;
        float v0 = sd[w][lane], v1 = sd[w][lane+32];
        float m = fmaxf(v0, v1);
        #pragma unroll
        for (int off = 16; off > 0; off >>= 1)
            m = fmaxf(m, __shfl_xor_sync(0xffffffffu, m, off));
        float e0 = __expf(v0 - m), e1 = __expf(v1 - m);
        float s = e0 + e1;
        #pragma unroll
        for (int off = 16; off > 0; off >>= 1)
            s += __shfl_xor_sync(0xffffffffu, s, off);
        float inv = 1.f / s;
        sd[w][lane]    = e0*inv;
        sd[w][lane+32] = e1*inv;
    }
    __syncthreads();

    // AV phase 1: thread (g = t>>6, d = t&63); v direct from global.
    {
        int g = t >> 6, d = t & 63;
        const float* vbase = g_v + ((size_t)b*Np*Hp + h)*Dp + d;
        float a0 = 0.f, a1 = 0.f, a2 = 0.f, a3 = 0.f;
        #pragma unroll
        for (int c = 0; c < 4; c++) {
            float4 s0 = *(const float4*)&sd[0][g*16 + c*4];
            float4 s1 = *(const float4*)&sd[1][g*16 + c*4];
            float4 s2 = *(const float4*)&sd[2][g*16 + c*4];
            float4 s3 = *(const float4*)&sd[3][g*16 + c*4];
            float sv0[4] = {s0.x, s0.y, s0.z, s0.w};
            float sv1[4] = {s1.x, s1.y, s1.z, s1.w};
            float sv2[4] = {s2.x, s2.y, s2.z, s2.w};
            float sv3[4] = {s3.x, s3.y, s3.z, s3.w};
            #pragma unroll
            for (int j = 0; j < 4; j++) {
                int z = g*16 + c*4 + j;
                int row = sidx[z];
                float vv = __ldg(vbase + (size_t)row*Hp*Dp);
                a0 += sv0[j] * vv;
                a1 += sv1[j] * vv;
                a2 += sv2[j] * vv;
                a3 += sv3[j] * vv;
            }
        }
        partial[g][0][d] = a0;
        partial[g][1][d] = a1;
        partial[g][2][d] = a2;
        partial[g][3][d] = a3;
    }
    __syncthreads();

    // AV phase 2: reduce 4 partials, write out
    {
        int w = t >> 6, d = t & 63;
        float acc = partial[0][w][d] + partial[1][w][d]
                  + partial[2][w][d] + partial[3][w][d];
        g_attn[((size_t)b*Np + nw*Wp + w)*(Hp*Dp) + h*Dp + d] = acc;
    }
}

// ---------------------------------------------------------------------------
extern "C" void kernel_launch(void* const* d_in, const int* in_sizes, int n_in,
                              void* d_out, int out_size)
{
    const float* x            = (const float*)d_in[0];
    const unsigned char* mask = (const unsigned char*)d_in[1];
    const float* pos_bias     = (const float*)d_in[2];
    const float* pareto       = (const float*)d_in[3];
    const float* Wqkv         = (const float*)d_in[4];
    const float* bqkv         = (const float*)d_in[5];
    const float* Wo           = (const float*)d_in[6];
    const float* bo           = (const float*)d_in[7];
    float* out                = (float*)d_out;

    (void)in_sizes; (void)n_in; (void)out_size;

    static cudaStream_t s2 = nullptr;
    static cudaEvent_t evFork = nullptr, evPerm = nullptr, evJoin = nullptr;
    if (s2 == nullptr) {
        cudaStreamCreateWithFlags(&s2, cudaStreamNonBlocking);
        cudaEventCreateWithFlags(&evFork, cudaEventDisableTiming);
        cudaEventCreateWithFlags(&evPerm, cudaEventDisableTiming);
        cudaEventCreateWithFlags(&evJoin, cudaEventDisableTiming);
        cudaFuncSetAttribute(gemm_tf32_kernel<0>,
            cudaFuncAttributeMaxDynamicSharedMemorySize, GEMM_SMEM);
        cudaFuncSetAttribute(gemm_tf32_kernel<1>,
            cudaFuncAttributeMaxDynamicSharedMemorySize, GEMM_SMEM);
    }

    // Fork side stream: weight permute, then selection.
    cudaEventRecord(evFork, 0);
    cudaStreamWaitEvent(s2, evFork, 0);
    permW_kernel<<<(Cp*3*Hp*Dp)/256, 256, 0, s2>>>(Wqkv, bqkv);
    cudaEventRecord(evPerm, s2);
    select_kernel<<<Bp*Hp*NWp, 256, 0, s2>>>(pareto, mask);
    cudaEventRecord(evJoin, s2);

    // QKV GEMM (needs permuted weights).
    cudaStreamWaitEvent(0, evPerm, 0);
    {
        dim3 grid(3*Hp*Dp/128, Bp*Np/128);   // 12 x 64
        gemm_tf32_kernel<0><<<grid, 256, GEMM_SMEM>>>(x, nullptr, nullptr, nullptr, 3*Hp*Dp);
    }

    // Attention (needs q/k/v and g_idx).
    cudaStreamWaitEvent(0, evJoin, 0);
    attn_kernel<<<Bp*Hp*NWp, 256>>>(pos_bias, mask);

    // Output projection.
    {
        dim3 grid(Cp/128, Bp*Np/128);        // 4 x 64
        gemm_tf32_kernel<1><<<grid, 256, GEMM_SMEM>>>(nullptr, Wo, bo, out, Cp);
    }
}

// round 9
// speedup vs baseline: 1.1504x; 1.0415x over previous
#include <cuda_runtime.h>
#include <math.h>
#include <stdint.h>

// Problem constants
#define Bp 4
#define Np 2048
#define Cp 512
#define Hp 8
#define Dp 64
#define Wp 4
#define NWp 512
#define KEEP 64

// Scratch (device globals; no allocation allowed)
__device__ float g_q[Bp*Np*Hp*Dp];       // [B,N,H,D]
__device__ float g_k[Bp*Np*Hp*Dp];
__device__ float g_v[Bp*Np*Hp*Dp];
__device__ float g_attn[Bp*Np*Hp*Dp];    // [B,N,H*D] (tf32-rounded values)
__device__ int   g_idx[Bp*Hp*NWp*KEEP];  // [B,H,NW,64]
__device__ float g_Wperm[Cp*3*Hp*Dp];    // Wqkv permuted to (s,h,d), tf32-rounded
__device__ float g_bperm[3*Hp*Dp];
__device__ float g_x32[Bp*Np*Cp];        // x, tf32-rounded
__device__ float g_Wo32[Cp*Cp];          // Wo, tf32-rounded

// ---------------------------------------------------------------------------
// tf32 / async-copy helpers
// ---------------------------------------------------------------------------
__device__ __forceinline__ float to_tf32(float x) {
    unsigned u;
    asm("cvt.rna.tf32.f32 %0, %1;" : "=r"(u) : "f"(x));
    return __uint_as_float(u);
}

__device__ __forceinline__ void mma_tf32(float4& d,
    unsigned a0, unsigned a1, unsigned a2, unsigned a3,
    unsigned b0, unsigned b1)
{
    asm volatile(
        "mma.sync.aligned.m16n8k8.row.col.f32.tf32.tf32.f32 "
        "{%0,%1,%2,%3}, {%4,%5,%6,%7}, {%8,%9}, {%0,%1,%2,%3};\n"
        : "+f"(d.x), "+f"(d.y), "+f"(d.z), "+f"(d.w)
        : "r"(a0), "r"(a1), "r"(a2), "r"(a3), "r"(b0), "r"(b1));
}

__device__ __forceinline__ void cp16(float* dst_smem, const float* src) {
    unsigned d = (unsigned)__cvta_generic_to_shared(dst_smem);
    asm volatile("cp.async.cg.shared.global [%0], [%1], 16;" :: "r"(d), "l"(src));
}
#define CP_COMMIT() asm volatile("cp.async.commit_group;")
#define CP_WAIT0()  asm volatile("cp.async.wait_group 0;")

// ---------------------------------------------------------------------------
// Producers: tf32-convert x / Wo; permute+convert Wqkv.
// ---------------------------------------------------------------------------
__global__ __launch_bounds__(256) void convX_kernel(const float* __restrict__ x)
{
    int i = blockIdx.x*256 + threadIdx.x;
    float4 v = *(const float4*)(x + (size_t)i*4);
    v.x = to_tf32(v.x); v.y = to_tf32(v.y); v.z = to_tf32(v.z); v.w = to_tf32(v.w);
    *(float4*)(g_x32 + (size_t)i*4) = v;
}

__global__ __launch_bounds__(256) void convWo_kernel(const float* __restrict__ Wo)
{
    int i = blockIdx.x*256 + threadIdx.x;
    float4 v = *(const float4*)(Wo + (size_t)i*4);
    v.x = to_tf32(v.x); v.y = to_tf32(v.y); v.z = to_tf32(v.z); v.w = to_tf32(v.w);
    *(float4*)(g_Wo32 + (size_t)i*4) = v;
}

__global__ __launch_bounds__(256) void permW_kernel(
    const float* __restrict__ Wqkv, const float* __restrict__ bqkv)
{
    int idx = blockIdx.x*256 + threadIdx.x;      // 0 .. 512*1536-1
    int u = idx % 1536;
    int k = idx / 1536;
    int s = u >> 9, hd = u & 511;
    g_Wperm[idx] = to_tf32(Wqkv[(size_t)k*1536 + hd*3 + s]);
    if (idx < 1536) g_bperm[idx] = bqkv[(idx & 511)*3 + (idx >> 9)];
}

// ---------------------------------------------------------------------------
// tf32 GEMM, cp.async double-buffered. Operands already tf32-rounded.
// ---------------------------------------------------------------------------
#define AS_STRIDE 36
#define BS_STRIDE 132
#define AS_STAGE (128*AS_STRIDE)
#define BS_STAGE (32*BS_STRIDE)
#define GEMM_SMEM ((2*AS_STAGE + 2*BS_STAGE)*4)  // 70656 bytes

template<int EPI>
__global__ __launch_bounds__(256, 2) void gemm_tf32_kernel(
    const float* __restrict__ biasIn,
    float* __restrict__ Cout,
    int Nn)
{
    extern __shared__ float smem[];
    float* AsB = smem;
    float* BsB = smem + 2*AS_STAGE;

    const int Kk = 512;
    const float* A    = (EPI == 0) ? (const float*)g_x32   : (const float*)g_attn;
    const float* Bw   = (EPI == 0) ? (const float*)g_Wperm : (const float*)g_Wo32;
    const float* bias = (EPI == 0) ? (const float*)g_bperm : biasIn;

    int tid = threadIdx.x;
    int bx = blockIdx.x, by = blockIdx.y;
    int warp = tid >> 5, lane = tid & 31;
    int wm = warp & 1, wn = warp >> 1;
    int gid = lane >> 2, tig = lane & 3;

    float4 acc[4][4];
    #pragma unroll
    for (int i = 0; i < 4; i++)
        #pragma unroll
        for (int j = 0; j < 4; j++) acc[i][j] = make_float4(0.f,0.f,0.f,0.f);

    // async-load tile kt into stage st
    auto load_tile = [&](int st, int kt) {
        int k0 = kt*32;
        float* As = AsB + st*AS_STAGE;
        float* Bs = BsB + st*BS_STAGE;
        #pragma unroll
        for (int i = 0; i < 4; i++) {
            int f = tid + i*256;
            cp16(&As[(f>>3)*AS_STRIDE + (f&7)*4],
                 A + (size_t)(by*128 + (f>>3))*Kk + k0 + (f&7)*4);
            cp16(&Bs[(f>>5)*BS_STRIDE + (f&31)*4],
                 Bw + (size_t)(k0 + (f>>5))*Nn + bx*128 + (f&31)*4);
        }
        CP_COMMIT();
    };

    load_tile(0, 0);
    CP_WAIT0();
    __syncthreads();

    int s = 0;
    for (int kt = 0; kt < 16; kt++) {
        if (kt < 15) load_tile(s^1, kt+1);

        const float* Asc = AsB + s*AS_STAGE;
        const float* Bsc = BsB + s*BS_STAGE;
        #pragma unroll
        for (int ks = 0; ks < 4; ks++) {
            int k0 = ks*8;
            unsigned af[4][4], bf[4][2];
            #pragma unroll
            for (int i = 0; i < 4; i++) {
                int r = wm*64 + i*16 + gid;
                af[i][0] = __float_as_uint(Asc[ r    *AS_STRIDE + k0 + tig]);
                af[i][1] = __float_as_uint(Asc[(r+8)*AS_STRIDE + k0 + tig]);
                af[i][2] = __float_as_uint(Asc[ r    *AS_STRIDE + k0 + tig + 4]);
                af[i][3] = __float_as_uint(Asc[(r+8)*AS_STRIDE + k0 + tig + 4]);
            }
            #pragma unroll
            for (int j = 0; j < 4; j++) {
                int c = wn*32 + j*8 + gid;
                bf[j][0] = __float_as_uint(Bsc[(k0 + tig    )*BS_STRIDE + c]);
                bf[j][1] = __float_as_uint(Bsc[(k0 + tig + 4)*BS_STRIDE + c]);
            }
            #pragma unroll
            for (int i = 0; i < 4; i++)
                #pragma unroll
                for (int j = 0; j < 4; j++)
                    mma_tf32(acc[i][j], af[i][0], af[i][1], af[i][2], af[i][3],
                             bf[j][0], bf[j][1]);
        }

        if (kt < 15) CP_WAIT0();
        __syncthreads();
        s ^= 1;
    }

    float* dst;
    int colBase, rowStride;
    if (EPI == 0) {
        int sq = bx >> 2;
        dst = (sq == 0) ? g_q : (sq == 1) ? g_k : g_v;
        colBase = (bx & 3)*128;
        rowStride = 512;
    } else {
        dst = Cout;
        colBase = bx*128;
        rowStride = Nn;
    }
    #pragma unroll
    for (int i = 0; i < 4; i++) {
        int m0 = by*128 + wm*64 + i*16 + gid;
        #pragma unroll
        for (int j = 0; j < 4; j++) {
            int cl = wn*32 + j*8 + tig*2;
            float bz0 = bias[bx*128 + cl];
            float bz1 = bias[bx*128 + cl + 1];
            float4 d = acc[i][j];
            float2 o0 = make_float2(d.x + bz0, d.y + bz1);
            float2 o1 = make_float2(d.z + bz0, d.w + bz1);
            *(float2*)(dst + (size_t)m0*rowStride + colBase + cl)     = o0;
            *(float2*)(dst + (size_t)(m0+8)*rowStride + colBase + cl) = o1;
        }
    }
}

// ---------------------------------------------------------------------------
// Block-wide inclusive scan (256 threads) via warp shuffles.
// ---------------------------------------------------------------------------
__device__ __forceinline__ unsigned blockScanIncl(unsigned v, unsigned* warpSums, int t)
{
    int lane = t & 31, wid = t >> 5;
    #pragma unroll
    for (int off = 1; off < 32; off <<= 1) {
        unsigned n = __shfl_up_sync(0xffffffffu, v, off);
        if (lane >= off) v += n;
    }
    if (lane == 31) warpSums[wid] = v;
    __syncthreads();
    if (wid == 0) {
        unsigned s = (lane < 8) ? warpSums[lane] : 0u;
        #pragma unroll
        for (int off = 1; off < 8; off <<= 1) {
            unsigned n = __shfl_up_sync(0xffffffffu, s, off);
            if (lane >= off) s += n;
        }
        if (lane < 8) warpSums[lane] = s;
    }
    __syncthreads();
    if (wid > 0) v += warpSums[wid - 1];
    return v;
}

template<int NB>
__device__ __forceinline__ void findThresholdBin(
    const unsigned* hist, unsigned r, unsigned* warpSums, unsigned* sOut, int t)
{
    const int PER = NB / 256;
    unsigned loc[PER];
    unsigned s = 0;
    #pragma unroll
    for (int i = 0; i < PER; i++) { loc[i] = hist[t*PER + i]; s += loc[i]; }
    unsigned incl = blockScanIncl(s, warpSums, t);
    unsigned excl = incl - s;
    if (excl < r && r <= incl) {
        unsigned cum = excl;
        #pragma unroll
        for (int i = 0; i < PER; i++) {
            if (cum + loc[i] >= r) { sOut[0] = t*PER + i; sOut[1] = cum; break; }
            cum += loc[i];
        }
    }
    __syncthreads();
}

// ---------------------------------------------------------------------------
// Selection: hierarchical radix-select (11/11/10 bits), stable sorted emit.
// ---------------------------------------------------------------------------
__global__ __launch_bounds__(256) void select_kernel(
    const float* __restrict__ pareto,        // [B,H,NW,N]
    const unsigned char* __restrict__ mask)  // [B,N] bool
{
    __shared__ unsigned hist[2048];
    __shared__ unsigned cand[2048];
    __shared__ unsigned warpSums[8];
    __shared__ unsigned sOut[2];
    __shared__ unsigned sCnt;

    int p = blockIdx.x;
    int nw = p & (NWp-1);
    int b  = p / (Hp*NWp);
    int t  = threadIdx.x;

    const float* prow = pareto + (size_t)p * Np;
    const unsigned char* mrow = mask + (size_t)b * Np;

    unsigned key[8];
    #pragma unroll
    for (int v = 0; v < 2; v++) {
        int j0 = t*8 + v*4;
        float4 nz = *(const float4*)(prow + j0);
        float noise[4] = {nz.x, nz.y, nz.z, nz.w};
        #pragma unroll
        for (int i = 0; i < 4; i++) {
            int j = j0 + i;
            int cj = j >> 2;
            float gridv = fabsf((float)(nw - cj));
            float val = gridv - noise[i];
            if (mrow[j]) val = 3.402823466e38f;
            unsigned ub = __float_as_uint(val);
            ub ^= (ub & 0x80000000u) ? 0xFFFFFFFFu : 0x80000000u;
            key[v*4 + i] = ub;
        }
    }

    #pragma unroll
    for (int i = 0; i < 8; i++) hist[t*8 + i] = 0;
    __syncthreads();
    #pragma unroll
    for (int i = 0; i < 8; i++)
        atomicAdd(&hist[key[i] >> 21], 1u);
    __syncthreads();

    unsigned r = 64;
    findThresholdBin<2048>(hist, r, warpSums, sOut, t);
    unsigned bin1 = sOut[0];
    r -= sOut[1];
    unsigned prefix = bin1 << 21;
    __syncthreads();

    if (t == 0) sCnt = 0;
    __syncthreads();
    #pragma unroll
    for (int i = 0; i < 8; i++)
        if ((key[i] >> 21) == bin1)
            cand[atomicAdd(&sCnt, 1u)] = key[i];
    __syncthreads();
    unsigned E = sCnt;

    {
        #pragma unroll
        for (int i = 0; i < 8; i++) hist[t*8 + i] = 0;
        unsigned kk[8]; int n = 0;
        for (unsigned j = t; j < E; j += 256) kk[n++] = cand[j];
        __syncthreads();
        for (int i = 0; i < n; i++)
            atomicAdd(&hist[(kk[i] >> 10) & 0x7FFu], 1u);
        __syncthreads();
        findThresholdBin<2048>(hist, r, warpSums, sOut, t);
        unsigned bin2 = sOut[0];
        r -= sOut[1];
        prefix |= bin2 << 10;
        __syncthreads();
        if (t == 0) sCnt = 0;
        __syncthreads();
        for (int i = 0; i < n; i++)
            if (((kk[i] >> 10) & 0x7FFu) == bin2)
                cand[atomicAdd(&sCnt, 1u)] = kk[i];
        __syncthreads();
        E = sCnt;
    }

    {
        #pragma unroll
        for (int i = 0; i < 4; i++) hist[t*4 + i] = 0;
        unsigned kk[8]; int n = 0;
        for (unsigned j = t; j < E; j += 256) kk[n++] = cand[j];
        __syncthreads();
        for (int i = 0; i < n; i++)
            atomicAdd(&hist[kk[i] & 0x3FFu], 1u);
        __syncthreads();
        findThresholdBin<1024>(hist, r, warpSums, sOut, t);
        unsigned bin3 = sOut[0];
        r -= sOut[1];
        prefix |= bin3;
        __syncthreads();
    }

    unsigned T = prefix;
    unsigned rr = r;

    unsigned lessC = 0, eqC = 0;
    #pragma unroll
    for (int i = 0; i < 8; i++) {
        lessC += (key[i] < T);
        eqC   += (key[i] == T);
    }
    unsigned packed = lessC | (eqC << 16);
    unsigned incl = blockScanIncl(packed, warpSums, t);
    unsigned lb = (incl & 0xFFFFu) - lessC;
    unsigned eb = (incl >> 16)     - eqC;

    int* oidx = g_idx + (size_t)p * KEEP;
    #pragma unroll
    for (int i = 0; i < 8; i++) {
        int j = t*8 + i;
        unsigned k = key[i];
        if (k < T) {
            oidx[lb + min(eb, rr)] = j;
            lb++;
        } else if (k == T) {
            if (eb < rr) oidx[lb + eb] = j;
            eb++;
        }
    }
}

// ---------------------------------------------------------------------------
// Attention: one block per (b,h,nw); 256 threads. q/k/v in [B,N,H,D].
// pb prefetched with warp-per-w map (sorted keys -> coalesced);
// K in registers, quad-shuffle dots; V direct from global in AV.
// ---------------------------------------------------------------------------
#define PADR 68
__global__ __launch_bounds__(256) void attn_kernel(
    const float* __restrict__ pos_bias,      // [H,N,N]
    const unsigned char* __restrict__ mask)  // [B,N]
{
    __shared__ int   sidx[KEEP];
    __shared__ float qs[Wp][PADR];
    __shared__ float sd[Wp][PADR];
    __shared__ float pb_s[Wp][PADR];
    __shared__ unsigned char km_s[KEEP];
    __shared__ float partial[4][Wp][Dp];

    int p  = blockIdx.x;
    int nw = p & (NWp-1);
    int bh = p >> 9;
    int h  = bh & (Hp-1);
    int b  = bh >> 3;
    int t  = threadIdx.x;

    if (t < KEEP) sidx[t] = g_idx[(size_t)p * KEEP + t];
    {
        int w = t >> 6, d = t & 63;
        qs[w][d] = g_q[((size_t)(b*Np + nw*Wp + w)*Hp + h)*Dp + d];
    }
    __syncthreads();

    // pb prefetch: warp-major w, 32 consecutive (sorted) z per warp.
    {
        int w = t >> 6, z = t & 63;
        int key = sidx[z];
        pb_s[w][z] = __ldg(pos_bias + ((size_t)h*Np + nw*Wp + w)*Np + key);
        if (t < KEEP) km_s[t] = mask[(size_t)b*Np + sidx[t]];
    }
    __syncthreads();

    // Fused gather+dots: thread (z = t>>2, quar = t&3).
    const float scale = 0.125f;
    {
        int z = t >> 2, quar = t & 3;
        int row = sidx[z];
        const float* kp = g_k + ((size_t)(b*Np + row)*Hp + h)*Dp + quar*16;
        float4 kv[4];
        #pragma unroll
        for (int i = 0; i < 4; i++) kv[i] = __ldg((const float4*)(kp + i*4));

        bool qm = mask[(size_t)b*Np + nw*Wp + quar] != 0;

        float pw[4] = {0.f, 0.f, 0.f, 0.f};
        #pragma unroll
        for (int i = 0; i < 4; i++) {
            #pragma unroll
            for (int w = 0; w < 4; w++) {
                float4 qv = *(const float4*)&qs[w][quar*16 + i*4];
                pw[w] += qv.x*kv[i].x + qv.y*kv[i].y + qv.z*kv[i].z + qv.w*kv[i].w;
            }
        }
        #pragma unroll
        for (int w = 0; w < 4; w++) {
            pw[w] += __shfl_xor_sync(0xffffffffu, pw[w], 1);
            pw[w] += __shfl_xor_sync(0xffffffffu, pw[w], 2);
        }
        float val = pw[quar]*scale + pb_s[quar][z];
        if (qm && km_s[z]) val = -3.402823466e38f;
        sd[quar][z] = val;
    }
    __syncthreads();

    // Softmax: warp w (w<4) owns row w
    if (t < 128) {
        int w = t >> 5, lane = t & 31;
        float v0 = sd[w][lane], v1 = sd[w][lane+32];
        float m = fmaxf(v0, v1);
        #pragma unroll
        for (int off = 16; off > 0; off >>= 1)
            m = fmaxf(m, __shfl_xor_sync(0xffffffffu, m, off));
        float e0 = __expf(v0 - m), e1 = __expf(v1 - m);
        float s = e0 + e1;
        #pragma unroll
        for (int off = 16; off > 0; off >>= 1)
            s += __shfl_xor_sync(0xffffffffu, s, off);
        float inv = 1.f / s;
        sd[w][lane]    = e0*inv;
        sd[w][lane+32] = e1*inv;
    }
    __syncthreads();

    // AV phase 1: thread (g = t>>6, d = t&63); v direct from global.
    {
        int g = t >> 6, d = t & 63;
        const float* vbase = g_v + ((size_t)b*Np*Hp + h)*Dp + d;
        float a0 = 0.f, a1 = 0.f, a2 = 0.f, a3 = 0.f;
        #pragma unroll
        for (int c = 0; c < 4; c++) {
            float4 s0 = *(const float4*)&sd[0][g*16 + c*4];
            float4 s1 = *(const float4*)&sd[1][g*16 + c*4];
            float4 s2 = *(const float4*)&sd[2][g*16 + c*4];
            float4 s3 = *(const float4*)&sd[3][g*16 + c*4];
            float sv0[4] = {s0.x, s0.y, s0.z, s0.w};
            float sv1[4] = {s1.x, s1.y, s1.z, s1.w};
            float sv2[4] = {s2.x, s2.y, s2.z, s2.w};
            float sv3[4] = {s3.x, s3.y, s3.z, s3.w};
            #pragma unroll
            for (int j = 0; j < 4; j++) {
                int z = g*16 + c*4 + j;
                int row = sidx[z];
                float vv = __ldg(vbase + (size_t)row*Hp*Dp);
                a0 += sv0[j] * vv;
                a1 += sv1[j] * vv;
                a2 += sv2[j] * vv;
                a3 += sv3[j] * vv;
            }
        }
        partial[g][0][d] = a0;
        partial[g][1][d] = a1;
        partial[g][2][d] = a2;
        partial[g][3][d] = a3;
    }
    __syncthreads();

    // AV phase 2: reduce 4 partials, write out (tf32-rounded for gemm<1>)
    {
        int w = t >> 6, d = t & 63;
        float acc = partial[0][w][d] + partial[1][w][d]
                  + partial[2][w][d] + partial[3][w][d];
        g_attn[((size_t)b*Np + nw*Wp + w)*(Hp*Dp) + h*Dp + d] = to_tf32(acc);
    }
}

// ---------------------------------------------------------------------------
extern "C" void kernel_launch(void* const* d_in, const int* in_sizes, int n_in,
                              void* d_out, int out_size)
{
    const float* x            = (const float*)d_in[0];
    const unsigned char* mask = (const unsigned char*)d_in[1];
    const float* pos_bias     = (const float*)d_in[2];
    const float* pareto       = (const float*)d_in[3];
    const float* Wqkv         = (const float*)d_in[4];
    const float* bqkv         = (const float*)d_in[5];
    const float* Wo           = (const float*)d_in[6];
    const float* bo           = (const float*)d_in[7];
    float* out                = (float*)d_out;

    (void)in_sizes; (void)n_in; (void)out_size;

    static cudaStream_t s2 = nullptr;
    static cudaEvent_t evFork = nullptr, evPerm = nullptr, evJoin = nullptr;
    if (s2 == nullptr) {
        cudaStreamCreateWithFlags(&s2, cudaStreamNonBlocking);
        cudaEventCreateWithFlags(&evFork, cudaEventDisableTiming);
        cudaEventCreateWithFlags(&evPerm, cudaEventDisableTiming);
        cudaEventCreateWithFlags(&evJoin, cudaEventDisableTiming);
        cudaFuncSetAttribute(gemm_tf32_kernel<0>,
            cudaFuncAttributeMaxDynamicSharedMemorySize, GEMM_SMEM);
        cudaFuncSetAttribute(gemm_tf32_kernel<1>,
            cudaFuncAttributeMaxDynamicSharedMemorySize, GEMM_SMEM);
    }

    // Fork side stream: producers for gemm<0>, then select, then Wo convert.
    cudaEventRecord(evFork, 0);
    cudaStreamWaitEvent(s2, evFork, 0);
    permW_kernel<<<(Cp*3*Hp*Dp)/256, 256, 0, s2>>>(Wqkv, bqkv);
    convX_kernel<<<(Bp*Np*Cp/4)/256, 256, 0, s2>>>(x);
    cudaEventRecord(evPerm, s2);
    convWo_kernel<<<(Cp*Cp/4)/256, 256, 0, s2>>>(Wo);
    select_kernel<<<Bp*Hp*NWp, 256, 0, s2>>>(pareto, mask);
    cudaEventRecord(evJoin, s2);

    // QKV GEMM (needs g_x32 + g_Wperm).
    cudaStreamWaitEvent(0, evPerm, 0);
    {
        dim3 grid(3*Hp*Dp/128, Bp*Np/128);   // 12 x 64
        gemm_tf32_kernel<0><<<grid, 256, GEMM_SMEM>>>(nullptr, nullptr, 3*Hp*Dp);
    }

    // Attention (needs q/k/v, g_idx; join also covers g_Wo32 for gemm<1>).
    cudaStreamWaitEvent(0, evJoin, 0);
    attn_kernel<<<Bp*Hp*NWp, 256>>>(pos_bias, mask);

    // Output projection.
    {
        dim3 grid(Cp/128, Bp*Np/128);        // 4 x 64
        gemm_tf32_kernel<1><<<grid, 256, GEMM_SMEM>>>(bo, out, Cp);
    }
}

// round 10
// speedup vs baseline: 1.2295x; 1.0687x over previous
#include <cuda_runtime.h>
#include <math.h>
#include <stdint.h>

// Problem constants
#define Bp 4
#define Np 2048
#define Cp 512
#define Hp 8
#define Dp 64
#define Wp 4
#define NWp 512
#define KEEP 64

// Scratch (device globals; no allocation allowed)
__device__ float g_q[Bp*Np*Hp*Dp];       // [B,N,H,D]
__device__ float g_k[Bp*Np*Hp*Dp];
__device__ float g_v[Bp*Np*Hp*Dp];
__device__ float g_attn[Bp*Np*Hp*Dp];    // [B,N,H*D] (tf32-rounded values)
__device__ int   g_idx[Bp*Hp*NWp*KEEP];  // [B,H,NW,64]
__device__ float g_Wperm[Cp*3*Hp*Dp];    // Wqkv permuted to (s,h,d), tf32-rounded
__device__ float g_bperm[3*Hp*Dp];
__device__ float g_x32[Bp*Np*Cp];        // x, tf32-rounded
__device__ float g_Wo32[Cp*Cp];          // Wo, tf32-rounded

// ---------------------------------------------------------------------------
// tf32 / async-copy helpers
// ---------------------------------------------------------------------------
__device__ __forceinline__ float to_tf32(float x) {
    unsigned u;
    asm("cvt.rna.tf32.f32 %0, %1;" : "=r"(u) : "f"(x));
    return __uint_as_float(u);
}

__device__ __forceinline__ void mma_tf32(float4& d,
    unsigned a0, unsigned a1, unsigned a2, unsigned a3,
    unsigned b0, unsigned b1)
{
    asm volatile(
        "mma.sync.aligned.m16n8k8.row.col.f32.tf32.tf32.f32 "
        "{%0,%1,%2,%3}, {%4,%5,%6,%7}, {%8,%9}, {%0,%1,%2,%3};\n"
        : "+f"(d.x), "+f"(d.y), "+f"(d.z), "+f"(d.w)
        : "r"(a0), "r"(a1), "r"(a2), "r"(a3), "r"(b0), "r"(b1));
}

__device__ __forceinline__ void cp16(float* dst_smem, const float* src) {
    unsigned d = (unsigned)__cvta_generic_to_shared(dst_smem);
    asm volatile("cp.async.cg.shared.global [%0], [%1], 16;" :: "r"(d), "l"(src));
}
#define CP_COMMIT() asm volatile("cp.async.commit_group;")
#define CP_WAIT0()  asm volatile("cp.async.wait_group 0;")

// ---------------------------------------------------------------------------
// Producers: tf32-convert x / Wo; permute+convert Wqkv.
// ---------------------------------------------------------------------------
__global__ __launch_bounds__(256) void convX_kernel(const float* __restrict__ x)
{
    int i = blockIdx.x*256 + threadIdx.x;
    float4 v = *(const float4*)(x + (size_t)i*4);
    v.x = to_tf32(v.x); v.y = to_tf32(v.y); v.z = to_tf32(v.z); v.w = to_tf32(v.w);
    *(float4*)(g_x32 + (size_t)i*4) = v;
}

__global__ __launch_bounds__(256) void convWo_kernel(const float* __restrict__ Wo)
{
    int i = blockIdx.x*256 + threadIdx.x;
    float4 v = *(const float4*)(Wo + (size_t)i*4);
    v.x = to_tf32(v.x); v.y = to_tf32(v.y); v.z = to_tf32(v.z); v.w = to_tf32(v.w);
    *(float4*)(g_Wo32 + (size_t)i*4) = v;
}

__global__ __launch_bounds__(256) void permW_kernel(
    const float* __restrict__ Wqkv, const float* __restrict__ bqkv)
{
    int idx = blockIdx.x*256 + threadIdx.x;      // 0 .. 512*1536-1
    int u = idx % 1536;
    int k = idx / 1536;
    int s = u >> 9, hd = u & 511;
    g_Wperm[idx] = to_tf32(Wqkv[(size_t)k*1536 + hd*3 + s]);
    if (idx < 1536) g_bperm[idx] = bqkv[(idx & 511)*3 + (idx >> 9)];
}

// ---------------------------------------------------------------------------
// tf32 GEMM, cp.async double-buffered. Operands already tf32-rounded.
// ---------------------------------------------------------------------------
#define AS_STRIDE 36
#define BS_STRIDE 132
#define AS_STAGE (128*AS_STRIDE)
#define BS_STAGE (32*BS_STRIDE)
#define GEMM_SMEM ((2*AS_STAGE + 2*BS_STAGE)*4)  // 70656 bytes

template<int EPI>
__global__ __launch_bounds__(256, 2) void gemm_tf32_kernel(
    const float* __restrict__ biasIn,
    float* __restrict__ Cout,
    int Nn)
{
    extern __shared__ float smem[];
    float* AsB = smem;
    float* BsB = smem + 2*AS_STAGE;

    const int Kk = 512;
    const float* A    = (EPI == 0) ? (const float*)g_x32   : (const float*)g_attn;
    const float* Bw   = (EPI == 0) ? (const float*)g_Wperm : (const float*)g_Wo32;
    const float* bias = (EPI == 0) ? (const float*)g_bperm : biasIn;

    int tid = threadIdx.x;
    int bx = blockIdx.x, by = blockIdx.y;
    int warp = tid >> 5, lane = tid & 31;
    int wm = warp & 1, wn = warp >> 1;
    int gid = lane >> 2, tig = lane & 3;

    float4 acc[4][4];
    #pragma unroll
    for (int i = 0; i < 4; i++)
        #pragma unroll
        for (int j = 0; j < 4; j++) acc[i][j] = make_float4(0.f,0.f,0.f,0.f);

    auto load_tile = [&](int st, int kt) {
        int k0 = kt*32;
        float* As = AsB + st*AS_STAGE;
        float* Bs = BsB + st*BS_STAGE;
        #pragma unroll
        for (int i = 0; i < 4; i++) {
            int f = tid + i*256;
            cp16(&As[(f>>3)*AS_STRIDE + (f&7)*4],
                 A + (size_t)(by*128 + (f>>3))*Kk + k0 + (f&7)*4);
            cp16(&Bs[(f>>5)*BS_STRIDE + (f&31)*4],
                 Bw + (size_t)(k0 + (f>>5))*Nn + bx*128 + (f&31)*4);
        }
        CP_COMMIT();
    };

    load_tile(0, 0);
    CP_WAIT0();
    __syncthreads();

    int s = 0;
    for (int kt = 0; kt < 16; kt++) {
        if (kt < 15) load_tile(s^1, kt+1);

        const float* Asc = AsB + s*AS_STAGE;
        const float* Bsc = BsB + s*BS_STAGE;
        #pragma unroll
        for (int ks = 0; ks < 4; ks++) {
            int k0 = ks*8;
            unsigned af[4][4], bf[4][2];
            #pragma unroll
            for (int i = 0; i < 4; i++) {
                int r = wm*64 + i*16 + gid;
                af[i][0] = __float_as_uint(Asc[ r    *AS_STRIDE + k0 + tig]);
                af[i][1] = __float_as_uint(Asc[(r+8)*AS_STRIDE + k0 + tig]);
                af[i][2] = __float_as_uint(Asc[ r    *AS_STRIDE + k0 + tig + 4]);
                af[i][3] = __float_as_uint(Asc[(r+8)*AS_STRIDE + k0 + tig + 4]);
            }
            #pragma unroll
            for (int j = 0; j < 4; j++) {
                int c = wn*32 + j*8 + gid;
                bf[j][0] = __float_as_uint(Bsc[(k0 + tig    )*BS_STRIDE + c]);
                bf[j][1] = __float_as_uint(Bsc[(k0 + tig + 4)*BS_STRIDE + c]);
            }
            #pragma unroll
            for (int i = 0; i < 4; i++)
                #pragma unroll
                for (int j = 0; j < 4; j++)
                    mma_tf32(acc[i][j], af[i][0], af[i][1], af[i][2], af[i][3],
                             bf[j][0], bf[j][1]);
        }

        if (kt < 15) CP_WAIT0();
        __syncthreads();
        s ^= 1;
    }

    float* dst;
    int colBase, rowStride;
    if (EPI == 0) {
        int sq = bx >> 2;
        dst = (sq == 0) ? g_q : (sq == 1) ? g_k : g_v;
        colBase = (bx & 3)*128;
        rowStride = 512;
    } else {
        dst = Cout;
        colBase = bx*128;
        rowStride = Nn;
    }
    #pragma unroll
    for (int i = 0; i < 4; i++) {
        int m0 = by*128 + wm*64 + i*16 + gid;
        #pragma unroll
        for (int j = 0; j < 4; j++) {
            int cl = wn*32 + j*8 + tig*2;
            float bz0 = bias[bx*128 + cl];
            float bz1 = bias[bx*128 + cl + 1];
            float4 d = acc[i][j];
            float2 o0 = make_float2(d.x + bz0, d.y + bz1);
            float2 o1 = make_float2(d.z + bz0, d.w + bz1);
            *(float2*)(dst + (size_t)m0*rowStride + colBase + cl)     = o0;
            *(float2*)(dst + (size_t)(m0+8)*rowStride + colBase + cl) = o1;
        }
    }
}

// ---------------------------------------------------------------------------
// Block-wide inclusive scan (256 threads) via warp shuffles.
// ---------------------------------------------------------------------------
__device__ __forceinline__ unsigned blockScanIncl(unsigned v, unsigned* warpSums, int t)
{
    int lane = t & 31, wid = t >> 5;
    #pragma unroll
    for (int off = 1; off < 32; off <<= 1) {
        unsigned n = __shfl_up_sync(0xffffffffu, v, off);
        if (lane >= off) v += n;
    }
    if (lane == 31) warpSums[wid] = v;
    __syncthreads();
    if (wid == 0) {
        unsigned s = (lane < 8) ? warpSums[lane] : 0u;
        #pragma unroll
        for (int off = 1; off < 8; off <<= 1) {
            unsigned n = __shfl_up_sync(0xffffffffu, s, off);
            if (lane >= off) s += n;
        }
        if (lane < 8) warpSums[lane] = s;
    }
    __syncthreads();
    if (wid > 0) v += warpSums[wid - 1];
    return v;
}

template<int NB>
__device__ __forceinline__ void findThresholdBin(
    const unsigned* hist, unsigned r, unsigned* warpSums, unsigned* sOut, int t)
{
    const int PER = NB / 256;
    unsigned loc[PER];
    unsigned s = 0;
    #pragma unroll
    for (int i = 0; i < PER; i++) { loc[i] = hist[t*PER + i]; s += loc[i]; }
    unsigned incl = blockScanIncl(s, warpSums, t);
    unsigned excl = incl - s;
    if (excl < r && r <= incl) {
        unsigned cum = excl;
        #pragma unroll
        for (int i = 0; i < PER; i++) {
            if (cum + loc[i] >= r) { sOut[0] = t*PER + i; sOut[1] = cum; break; }
            cum += loc[i];
        }
    }
    __syncthreads();
}

// ---------------------------------------------------------------------------
// Selection: pass-1 11-bit radix + exact rank-count on candidates.
// Stable sorted emit -> g_idx. Fallback refinement pass if candidates > 256.
// ---------------------------------------------------------------------------
__global__ __launch_bounds__(256) void select_kernel(
    const float* __restrict__ pareto,        // [B,H,NW,N]
    const unsigned char* __restrict__ mask)  // [B,N] bool
{
    __shared__ unsigned hist[2048];
    __shared__ unsigned cand[2048];
    __shared__ unsigned warpSums[8];
    __shared__ unsigned sOut[2];
    __shared__ unsigned sCnt;
    __shared__ unsigned sT, sRR;

    int p = blockIdx.x;
    int nw = p & (NWp-1);
    int b  = p / (Hp*NWp);
    int t  = threadIdx.x;

    const float* prow = pareto + (size_t)p * Np;
    const unsigned char* mrow = mask + (size_t)b * Np;

    // Build order-preserving uint keys (8 per thread). cj is constant per
    // float4 group: cj = t*2 + v. Mask: one 8-byte load.
    unsigned long long mbits = *(const unsigned long long*)(mrow + t*8);
    unsigned key[8];
    #pragma unroll
    for (int v = 0; v < 2; v++) {
        float4 nz = *(const float4*)(prow + t*8 + v*4);
        float noise[4] = {nz.x, nz.y, nz.z, nz.w};
        int ag = nw - (t*2 + v); if (ag < 0) ag = -ag;
        float gridv = (float)ag;
        #pragma unroll
        for (int i = 0; i < 4; i++) {
            float val = gridv - noise[i];
            if ((mbits >> ((v*4 + i)*8)) & 0xFFull) val = 3.402823466e38f;
            unsigned ub = __float_as_uint(val);
            ub ^= ((unsigned)((int)ub >> 31)) | 0x80000000u;
            key[v*4 + i] = ub;
        }
    }

    // ---- Pass 1: top 11 bits, histogram over all 2048 keys ----
    #pragma unroll
    for (int i = 0; i < 8; i++) hist[t*8 + i] = 0;
    __syncthreads();
    #pragma unroll
    for (int i = 0; i < 8; i++)
        atomicAdd(&hist[key[i] >> 21], 1u);
    __syncthreads();

    unsigned r = 64;
    findThresholdBin<2048>(hist, r, warpSums, sOut, t);
    unsigned bin1 = sOut[0];
    r -= sOut[1];
    __syncthreads();

    if (t == 0) sCnt = 0;
    __syncthreads();
    #pragma unroll
    for (int i = 0; i < 8; i++)
        if ((key[i] >> 21) == bin1)
            cand[atomicAdd(&sCnt, 1u)] = key[i];
    __syncthreads();
    unsigned E = sCnt;

    // ---- Fallback: refine with bits [10,21) if candidate set is large ----
    if (E > 256) {
        #pragma unroll
        for (int i = 0; i < 8; i++) hist[t*8 + i] = 0;
        unsigned kk[8]; int n = 0;
        for (unsigned j = t; j < E; j += 256) kk[n++] = cand[j];
        __syncthreads();
        for (int i = 0; i < n; i++)
            atomicAdd(&hist[(kk[i] >> 10) & 0x7FFu], 1u);
        __syncthreads();
        findThresholdBin<2048>(hist, r, warpSums, sOut, t);
        unsigned bin2 = sOut[0];
        r -= sOut[1];
        __syncthreads();
        if (t == 0) sCnt = 0;
        __syncthreads();
        for (int i = 0; i < n; i++)
            if (((kk[i] >> 10) & 0x7FFu) == bin2)
                cand[atomicAdd(&sCnt, 1u)] = kk[i];
        __syncthreads();
        E = sCnt;
    }

    // ---- Exact rank-count: find r-th smallest among cand[0..E) ----
    // Inner reads are lockstep -> LDS broadcast. Winner writes T and the
    // tie quota rr = r - (#cand < T).
    for (unsigned e = t; e < E; e += 256) {
        unsigned ke = cand[e];
        unsigned less = 0, eq = 0;
        for (unsigned i = 0; i < E; i++) {
            unsigned ki = cand[i];
            less += (ki < ke);
            eq   += (ki == ke);
        }
        if (less < r && r <= less + eq) { sT = ke; sRR = r - less; }
    }
    __syncthreads();
    unsigned T = sT;
    unsigned rr = sRR;

    // Stable keep-scan over all keys, packed block scan
    unsigned lessC = 0, eqC = 0;
    #pragma unroll
    for (int i = 0; i < 8; i++) {
        lessC += (key[i] < T);
        eqC   += (key[i] == T);
    }
    unsigned packed = lessC | (eqC << 16);
    unsigned incl = blockScanIncl(packed, warpSums, t);
    unsigned lb = (incl & 0xFFFFu) - lessC;
    unsigned eb = (incl >> 16)     - eqC;

    int* oidx = g_idx + (size_t)p * KEEP;
    #pragma unroll
    for (int i = 0; i < 8; i++) {
        int j = t*8 + i;
        unsigned k = key[i];
        if (k < T) {
            oidx[lb + min(eb, rr)] = j;
            lb++;
        } else if (k == T) {
            if (eb < rr) oidx[lb + eb] = j;
            eb++;
        }
    }
}

// ---------------------------------------------------------------------------
// Attention: one block per (b,h,nw); 256 threads. q/k/v in [B,N,H,D].
// ---------------------------------------------------------------------------
#define PADR 68
__global__ __launch_bounds__(256) void attn_kernel(
    const float* __restrict__ pos_bias,      // [H,N,N]
    const unsigned char* __restrict__ mask)  // [B,N]
{
    __shared__ int   sidx[KEEP];
    __shared__ float qs[Wp][PADR];
    __shared__ float sd[Wp][PADR];
    __shared__ float pb_s[Wp][PADR];
    __shared__ unsigned char km_s[KEEP];
    __shared__ float partial[4][Wp][Dp];

    int p  = blockIdx.x;
    int nw = p & (NWp-1);
    int bh = p >> 9;
    int h  = bh & (Hp-1);
    int b  = bh >> 3;
    int t  = threadIdx.x;

    if (t < KEEP) sidx[t] = g_idx[(size_t)p * KEEP + t];
    {
        int w = t >> 6, d = t & 63;
        qs[w][d] = g_q[((size_t)(b*Np + nw*Wp + w)*Hp + h)*Dp + d];
    }
    __syncthreads();

    {
        int w = t >> 6, z = t & 63;
        int key = sidx[z];
        pb_s[w][z] = __ldg(pos_bias + ((size_t)h*Np + nw*Wp + w)*Np + key);
        if (t < KEEP) km_s[t] = mask[(size_t)b*Np + sidx[t]];
    }
    __syncthreads();

    const float scale = 0.125f;
    {
        int z = t >> 2, quar = t & 3;
        int row = sidx[z];
        const float* kp = g_k + ((size_t)(b*Np + row)*Hp + h)*Dp + quar*16;
        float4 kv[4];
        #pragma unroll
        for (int i = 0; i < 4; i++) kv[i] = __ldg((const float4*)(kp + i*4));

        bool qm = mask[(size_t)b*Np + nw*Wp + quar] != 0;

        float pw[4] = {0.f, 0.f, 0.f, 0.f};
        #pragma unroll
        for (int i = 0; i < 4; i++) {
            #pragma unroll
            for (int w = 0; w < 4; w++) {
                float4 qv = *(const float4*)&qs[w][quar*16 + i*4];
                pw[w] += qv.x*kv[i].x + qv.y*kv[i].y + qv.z*kv[i].z + qv.w*kv[i].w;
            }
        }
        #pragma unroll
        for (int w = 0; w < 4; w++) {
            pw[w] += __shfl_xor_sync(0xffffffffu, pw[w], 1);
            pw[w] += __shfl_xor_sync(0xffffffffu, pw[w], 2);
        }
        float val = pw[quar]*scale + pb_s[quar][z];
        if (qm && km_s[z]) val = -3.402823466e38f;
        sd[quar][z] = val;
    }
    __syncthreads();

    if (t < 128) {
        int w = t >> 5, lane = t & 31;
        float v0 = sd[w][lane], v1 = sd[w][lane+32];
        float m = fmaxf(v0, v1);
        #pragma unroll
        for (int off = 16; off > 0; off >>= 1)
            m = fmaxf(m, __shfl_xor_sync(0xffffffffu, m, off));
        float e0 = __expf(v0 - m), e1 = __expf(v1 - m);
        float s = e0 + e1;
        #pragma unroll
        for (int off = 16; off > 0; off >>= 1)
            s += __shfl_xor_sync(0xffffffffu, s, off);
        float inv = 1.f / s;
        sd[w][lane]    = e0*inv;
        sd[w][lane+32] = e1*inv;
    }
    __syncthreads();

    {
        int g = t >> 6, d = t & 63;
        const float* vbase = g_v + ((size_t)b*Np*Hp + h)*Dp + d;
        float a0 = 0.f, a1 = 0.f, a2 = 0.f, a3 = 0.f;
        #pragma unroll
        for (int c = 0; c < 4; c++) {
            float4 s0 = *(const float4*)&sd[0][g*16 + c*4];
            float4 s1 = *(const float4*)&sd[1][g*16 + c*4];
            float4 s2 = *(const float4*)&sd[2][g*16 + c*4];
            float4 s3 = *(const float4*)&sd[3][g*16 + c*4];
            float sv0[4] = {s0.x, s0.y, s0.z, s0.w};
            float sv1[4] = {s1.x, s1.y, s1.z, s1.w};
            float sv2[4] = {s2.x, s2.y, s2.z, s2.w};
            float sv3[4] = {s3.x, s3.y, s3.z, s3.w};
            #pragma unroll
            for (int j = 0; j < 4; j++) {
                int z = g*16 + c*4 + j;
                int row = sidx[z];
                float vv = __ldg(vbase + (size_t)row*Hp*Dp);
                a0 += sv0[j] * vv;
                a1 += sv1[j] * vv;
                a2 += sv2[j] * vv;
                a3 += sv3[j] * vv;
            }
        }
        partial[g][0][d] = a0;
        partial[g][1][d] = a1;
        partial[g][2][d] = a2;
        partial[g][3][d] = a3;
    }
    __syncthreads();

    {
        int w = t >> 6, d = t & 63;
        float acc = partial[0][w][d] + partial[1][w][d]
                  + partial[2][w][d] + partial[3][w][d];
        g_attn[((size_t)b*Np + nw*Wp + w)*(Hp*Dp) + h*Dp + d] = to_tf32(acc);
    }
}

// ---------------------------------------------------------------------------
extern "C" void kernel_launch(void* const* d_in, const int* in_sizes, int n_in,
                              void* d_out, int out_size)
{
    const float* x            = (const float*)d_in[0];
    const unsigned char* mask = (const unsigned char*)d_in[1];
    const float* pos_bias     = (const float*)d_in[2];
    const float* pareto       = (const float*)d_in[3];
    const float* Wqkv         = (const float*)d_in[4];
    const float* bqkv         = (const float*)d_in[5];
    const float* Wo           = (const float*)d_in[6];
    const float* bo           = (const float*)d_in[7];
    float* out                = (float*)d_out;

    (void)in_sizes; (void)n_in; (void)out_size;

    static cudaStream_t s2 = nullptr;
    static cudaEvent_t evFork = nullptr, evPerm = nullptr, evJoin = nullptr;
    if (s2 == nullptr) {
        cudaStreamCreateWithFlags(&s2, cudaStreamNonBlocking);
        cudaEventCreateWithFlags(&evFork, cudaEventDisableTiming);
        cudaEventCreateWithFlags(&evPerm, cudaEventDisableTiming);
        cudaEventCreateWithFlags(&evJoin, cudaEventDisableTiming);
        cudaFuncSetAttribute(gemm_tf32_kernel<0>,
            cudaFuncAttributeMaxDynamicSharedMemorySize, GEMM_SMEM);
        cudaFuncSetAttribute(gemm_tf32_kernel<1>,
            cudaFuncAttributeMaxDynamicSharedMemorySize, GEMM_SMEM);
    }

    // Fork side stream: producers for gemm<0>, select, then Wo convert.
    cudaEventRecord(evFork, 0);
    cudaStreamWaitEvent(s2, evFork, 0);
    permW_kernel<<<(Cp*3*Hp*Dp)/256, 256, 0, s2>>>(Wqkv, bqkv);
    convX_kernel<<<(Bp*Np*Cp/4)/256, 256, 0, s2>>>(x);
    cudaEventRecord(evPerm, s2);
    select_kernel<<<Bp*Hp*NWp, 256, 0, s2>>>(pareto, mask);
    convWo_kernel<<<(Cp*Cp/4)/256, 256, 0, s2>>>(Wo);
    cudaEventRecord(evJoin, s2);

    // QKV GEMM (needs g_x32 + g_Wperm).
    cudaStreamWaitEvent(0, evPerm, 0);
    {
        dim3 grid(3*Hp*Dp/128, Bp*Np/128);   // 12 x 64
        gemm_tf32_kernel<0><<<grid, 256, GEMM_SMEM>>>(nullptr, nullptr, 3*Hp*Dp);
    }

    // Attention (needs q/k/v, g_idx; join also covers g_Wo32 for gemm<1>).
    cudaStreamWaitEvent(0, evJoin, 0);
    attn_kernel<<<Bp*Hp*NWp, 256>>>(pos_bias, mask);

    // Output projection.
    {
        dim3 grid(Cp/128, Bp*Np/128);        // 4 x 64
        gemm_tf32_kernel<1><<<grid, 256, GEMM_SMEM>>>(bo, out, Cp);
    }
}